// round 6
// baseline (speedup 1.0000x reference)
#include <cuda_runtime.h>
#include <math.h>

#define BB 2
#define TT 2048
#define CC 1024
#define HH 16
#define DD 64
#define C3 3072
#define MM (BB*TT)          // 4096
#define YELEMS (BB*TT*CC)   // 4194304

#define BQ 128
#define QPSTR 72

// scratch (static device arrays: allocation-free)
__device__ float g_qkv[MM * C3];   // [B*T, 3C]
__device__ float g_yatt[MM * CC];  // [B*T, C]
__device__ float g_mask[HH * TT];  // [H, rel]

__device__ __forceinline__ unsigned f2tf32(float x) {
    unsigned r;
    asm("cvt.rna.tf32.f32 %0, %1;" : "=r"(r) : "f"(x));
    return r;
}
__device__ __forceinline__ float f2tf32f(float x) {
    return __uint_as_float(f2tf32(x));
}

__device__ __forceinline__ void mma_tf32(float c[4], unsigned a0, unsigned a1,
                                         unsigned a2, unsigned a3,
                                         unsigned b0, unsigned b1) {
    asm volatile(
        "mma.sync.aligned.m16n8k8.row.col.f32.tf32.tf32.f32 "
        "{%0,%1,%2,%3}, {%4,%5,%6,%7}, {%8,%9}, {%0,%1,%2,%3};"
        : "+f"(c[0]), "+f"(c[1]), "+f"(c[2]), "+f"(c[3])
        : "r"(a0), "r"(a1), "r"(a2), "r"(a3), "r"(b0), "r"(b1));
}

// FFMA-only exp2 for z <= 0 (clamped at -80). No MUFU.
__device__ __forceinline__ float fexp2(float z) {
    z = fmaxf(z, -80.0f);
    float r = z + 12582912.0f;
    int zi = __float_as_int(r) - 0x4B400000;
    float f = z - (r - 12582912.0f);
    float p = 1.3333558e-3f;
    p = fmaf(p, f, 9.6181291e-3f);
    p = fmaf(p, f, 5.5504109e-2f);
    p = fmaf(p, f, 2.4022651e-1f);
    p = fmaf(p, f, 6.9314718e-1f);
    p = fmaf(p, f, 1.0f);
    return __int_as_float(__float_as_int(p) + (zi << 23));
}

// ---------------------------------------------------------------------------
// Pipelined tf32 tensor-core GEMM, conflict-free vectorized smem stores.
// Block 128x128, K-step 64, double-buffered. 256 threads, 8 warps (4x2),
// warp tile 32x64.
// Layouts (both tiles, 16B-chunk XOR swizzle): phys16 = (c&~7)|((c^(row&7))&7)
//  A [128 rows][64 k-permuted]: chunk c holds k = {b, b+4, b+1, b+5},
//    b = (c>>1)*8 + (c&1)*2.  Stores: STS.128, 4 phases. Frag: LDS.64 pairs.
//  B [64 k][128 n-permuted]: chunk c holds n = n0+{0,8,16,24},
//    n0 = (c&16)*4 + (c&1)*32 + ((c&15)>>1). Stores STS.128 4-phase,
//    frag LDS.128 4-phase.
// ---------------------------------------------------------------------------
#define GA_STG (128 * 64)
#define GB_STG (64 * 128)
#define GEMM_SMEM ((2 * GA_STG + 2 * GB_STG) * 4)   // 131072 bytes

__global__ __launch_bounds__(256, 1) void mma_gemm_pipe(
    const float* __restrict__ A, const float* __restrict__ W,
    const float* __restrict__ bias, float* __restrict__ out,
    int M, int N, int K)
{
    extern __shared__ float gsm[];
    float* Asm = gsm;                 // 2 stages 128x64
    float* Bsm = gsm + 2 * GA_STG;    // 2 stages 64x128

    const int tid = threadIdx.x;
    const int m0 = blockIdx.y * 128, n0 = blockIdx.x * 128;
    const int lane = tid & 31, w = tid >> 5;
    const int wM = w >> 1, wN = w & 1;
    const int g = lane >> 2, tig = lane & 3;

    // loaders
    const int arow = tid >> 1, ahalf = tid & 1;     // A: 128 rows, 2 halves of 32 k
    const int brow = tid >> 2, bq = tid & 3;        // B: 64 k-rows, 4 quarters

    const float* ag = &A[(size_t)(m0 + arow) * K];
    const float* bgb = &W[(size_t)brow * N + n0];

    float2 a2[16];      // 8 chunks x (lo,hi)
    float bv[8][4];     // 8 chunks x 4 vals

    // ---- tile-0 gmem loads
#pragma unroll
    for (int u = 0; u < 8; u++) {
        int c = ahalf * 8 + u;
        int b = ((c >> 1) << 3) + ((c & 1) << 1);
        a2[2 * u]     = *(const float2*)&ag[b];
        a2[2 * u + 1] = *(const float2*)&ag[b + 4];
    }
#pragma unroll
    for (int j = 0; j < 8; j++) {
        int c = bq * 8 + j;
        int nb = ((c & 16) << 2) + ((c & 1) << 5) + ((c & 15) >> 1);
#pragma unroll
        for (int s = 0; s < 4; s++) bv[j][s] = bgb[nb + 8 * s];
    }
    // ---- store tile 0 -> stage 0
    {
#pragma unroll
        for (int u = 0; u < 8; u++) {
            int c = ahalf * 8 + u;
            int phys = (c & ~7) | ((c ^ (arow & 7)) & 7);
            float4 v = {f2tf32f(a2[2*u].x), f2tf32f(a2[2*u+1].x),
                        f2tf32f(a2[2*u].y), f2tf32f(a2[2*u+1].y)};
            *(float4*)&Asm[arow * 64 + phys * 4] = v;
        }
#pragma unroll
        for (int j = 0; j < 8; j++) {
            int c = bq * 8 + j;
            int phys = (c & ~7) | ((c ^ (brow & 7)) & 7);
            float4 v = {f2tf32f(bv[j][0]), f2tf32f(bv[j][1]),
                        f2tf32f(bv[j][2]), f2tf32f(bv[j][3])};
            *(float4*)&Bsm[brow * 128 + phys * 4] = v;
        }
    }
    __syncthreads();

    float acc[2][8][4];
#pragma unroll
    for (int i = 0; i < 2; i++)
#pragma unroll
        for (int j = 0; j < 8; j++)
#pragma unroll
            for (int c = 0; c < 4; c++) acc[i][j][c] = 0.0f;

    const int NIT = K >> 6;
    for (int it = 0; it < NIT; it++) {
        // prefetch next tile
        if (it + 1 < NIT) {
            const float* ag2 = ag + (it + 1) * 64;
            const float* bg2 = bgb + (size_t)(it + 1) * 64 * N;
#pragma unroll
            for (int u = 0; u < 8; u++) {
                int c = ahalf * 8 + u;
                int b = ((c >> 1) << 3) + ((c & 1) << 1);
                a2[2 * u]     = *(const float2*)&ag2[b];
                a2[2 * u + 1] = *(const float2*)&ag2[b + 4];
            }
#pragma unroll
            for (int j = 0; j < 8; j++) {
                int c = bq * 8 + j;
                int nb = ((c & 16) << 2) + ((c & 1) << 5) + ((c & 15) >> 1);
#pragma unroll
                for (int s = 0; s < 4; s++) bv[j][s] = bg2[nb + 8 * s];
            }
        }

        // compute current stage
        const float* as = Asm + (it & 1) * GA_STG;
        const float* bs = Bsm + (it & 1) * GB_STG;
#pragma unroll
        for (int ka = 0; ka < 8; ka++) {
            unsigned a[2][4];
            {
                int c = 2 * ka + (tig >> 1);
                int off = (tig & 1) * 2;
                int phys = (c & ~7) | ((c ^ (g & 7)) & 7);   // row&7 == g for all 4 rows
#pragma unroll
                for (int i = 0; i < 2; i++) {
                    int r = wM * 32 + i * 16 + g;
                    float2 v0 = *(const float2*)&as[r * 64 + phys * 4 + off];
                    float2 v1 = *(const float2*)&as[(r + 8) * 64 + phys * 4 + off];
                    a[i][0] = __float_as_uint(v0.x);
                    a[i][1] = __float_as_uint(v1.x);
                    a[i][2] = __float_as_uint(v0.y);
                    a[i][3] = __float_as_uint(v1.y);
                }
            }
            unsigned b0[8], b1[8];
            {
                int c0 = 16 * wN + 2 * g;
                int r0 = (8 * ka + tig) * 128;
                int r1 = (8 * ka + tig + 4) * 128;
                int t0 = tig & 7, t1 = (tig + 4) & 7;
                float4 p0 = *(const float4*)&bs[r0 + (((c0 & ~7) | ((c0 ^ t0) & 7)) << 2)];
                float4 p1 = *(const float4*)&bs[r0 + ((((c0+1) & ~7) | (((c0+1) ^ t0) & 7)) << 2)];
                float4 q0 = *(const float4*)&bs[r1 + (((c0 & ~7) | ((c0 ^ t1) & 7)) << 2)];
                float4 q1 = *(const float4*)&bs[r1 + ((((c0+1) & ~7) | (((c0+1) ^ t1) & 7)) << 2)];
                b0[0] = __float_as_uint(p0.x); b0[1] = __float_as_uint(p0.y);
                b0[2] = __float_as_uint(p0.z); b0[3] = __float_as_uint(p0.w);
                b0[4] = __float_as_uint(p1.x); b0[5] = __float_as_uint(p1.y);
                b0[6] = __float_as_uint(p1.z); b0[7] = __float_as_uint(p1.w);
                b1[0] = __float_as_uint(q0.x); b1[1] = __float_as_uint(q0.y);
                b1[2] = __float_as_uint(q0.z); b1[3] = __float_as_uint(q0.w);
                b1[4] = __float_as_uint(q1.x); b1[5] = __float_as_uint(q1.y);
                b1[6] = __float_as_uint(q1.z); b1[7] = __float_as_uint(q1.w);
            }
#pragma unroll
            for (int i = 0; i < 2; i++)
#pragma unroll
                for (int j = 0; j < 8; j++)
                    mma_tf32(acc[i][j], a[i][0], a[i][1], a[i][2], a[i][3],
                             b0[j], b1[j]);
        }

        // store next tile into the other stage
        if (it + 1 < NIT) {
            float* asn = Asm + ((it + 1) & 1) * GA_STG;
            float* bsn = Bsm + ((it + 1) & 1) * GB_STG;
#pragma unroll
            for (int u = 0; u < 8; u++) {
                int c = ahalf * 8 + u;
                int phys = (c & ~7) | ((c ^ (arow & 7)) & 7);
                float4 v = {f2tf32f(a2[2*u].x), f2tf32f(a2[2*u+1].x),
                            f2tf32f(a2[2*u].y), f2tf32f(a2[2*u+1].y)};
                *(float4*)&asn[arow * 64 + phys * 4] = v;
            }
#pragma unroll
            for (int j = 0; j < 8; j++) {
                int c = bq * 8 + j;
                int phys = (c & ~7) | ((c ^ (brow & 7)) & 7);
                float4 v = {f2tf32f(bv[j][0]), f2tf32f(bv[j][1]),
                            f2tf32f(bv[j][2]), f2tf32f(bv[j][3])};
                *(float4*)&bsn[brow * 128 + phys * 4] = v;
            }
        }
        __syncthreads();
    }

    // epilogue: C frag rows (g, g+8), cols (2tig, 2tig+1)
#pragma unroll
    for (int i = 0; i < 2; i++) {
#pragma unroll
        for (int j = 0; j < 8; j++) {
            int row = m0 + wM * 32 + i * 16 + g;
            int col = n0 + wN * 64 + j * 8 + 2 * tig;
            float bx = bias[col], by = bias[col + 1];
            float2 o0 = {acc[i][j][0] + bx, acc[i][j][1] + by};
            float2 o1 = {acc[i][j][2] + bx, acc[i][j][3] + by};
            *(float2*)&out[(size_t)row * N + col] = o0;
            *(float2*)&out[(size_t)(row + 8) * N + col] = o1;
        }
    }
}

// ---------------------------------------------------------------------------
// mask table: g_mask[h][rel] = mpos(rel)*wave(rel)  (rel >= 0)
// ---------------------------------------------------------------------------
__global__ void maskgen(const float* __restrict__ sp, const float* __restrict__ pw,
                        const float* __restrict__ rw, float* __restrict__ mask)
{
    int h = blockIdx.x;
    float span   = 2048.0f / (1.0f + __expf(-sp[h]));
    float period = 2.0f + 2.0f / (1.0f + __expf(-pw[h]));
    float ratio  = -0.25f + 0.5f / (1.0f + __expf(-rw[h]));
    float amp = period * 0.25f, offs = period * ratio;
    for (int rel = threadIdx.x; rel < TT; rel += blockDim.x) {
        float relf = (float)rel;
        float mpos = fminf(fmaxf((32.0f - relf + span) * 0.03125f, 0.0f), 1.0f);
        float wave = 0.5f * (cosf(6.283185307179586f * relf / period) + 1.0f) * amp
                     + 0.5f + offs;
        wave = fminf(fmaxf(wave, 0.0f), 1.0f);
        mask[h * TT + rel] = mpos * wave;
    }
}

// ---------------------------------------------------------------------------
// Tensor-core flash attention (unchanged from R4, known-good).
// ---------------------------------------------------------------------------
__global__ __launch_bounds__(256) void attn_mma(
    const float* __restrict__ qkv, const float* __restrict__ span_p,
    const float* __restrict__ gmask, float* __restrict__ yout)
{
    extern __shared__ float sm[];
    float* QP = sm;                    // 128 x 72 (Q staging, then P)
    float* Ks = sm + BQ * QPSTR;       // 64 x 64
    float* Vs = Ks + 64 * 64;          // 64 x 64
    float* MT = Vs + 64 * 64;          // 2048 mask entries

    const int tid = threadIdx.x, lane = tid & 31, w = tid >> 5;
    const int g = lane >> 2, tig = lane & 3;
    const int i0 = ((int)gridDim.x - 1 - (int)blockIdx.x) * BQ;
    const int h = blockIdx.y, b = blockIdx.z;
    const int R = w * 16;
    const int fswz = (tig & 1) | ((tig & 2) << 1);

    for (int t = tid; t < TT; t += 256) MT[t] = gmask[h * TT + t];

    const float span = 2048.0f / (1.0f + __expf(-span_p[h]));

    {
        const float SC = 0.125f * 1.4426950408889634f;
        int row = tid >> 1, cb = (tid & 1) * 32;
        const float* src = &qkv[(size_t)(b * TT + i0 + row) * C3 + h * 64 + cb];
#pragma unroll
        for (int u = 0; u < 8; u++) {
            float4 v = *(const float4*)&src[u * 4];
            float vv[4] = {v.x, v.y, v.z, v.w};
#pragma unroll
            for (int c = 0; c < 4; c++) {
                int k = cb + u * 4 + c;
                int p8 = k & 7;
                int col = (k & ~7) | (((p8 & 3) << 1) | (p8 >> 2));
                QP[row * QPSTR + col] = f2tf32f(vv[c] * SC);
            }
        }
    }
    __syncthreads();

    unsigned qf[8][4];
#pragma unroll
    for (int ks = 0; ks < 8; ks++) {
        float2 v0 = *(const float2*)&QP[(R + g) * QPSTR + 8 * ks + 2 * tig];
        float2 v1 = *(const float2*)&QP[(R + g + 8) * QPSTR + 8 * ks + 2 * tig];
        qf[ks][0] = __float_as_uint(v0.x);
        qf[ks][1] = __float_as_uint(v1.x);
        qf[ks][2] = __float_as_uint(v0.y);
        qf[ks][3] = __float_as_uint(v1.y);
    }

    float O[8][4];
#pragma unroll
    for (int a = 0; a < 8; a++)
#pragma unroll
        for (int c = 0; c < 4; c++) O[a][c] = 0.0f;
    float mr[2] = {-1e30f, -1e30f}, lr[2] = {0.0f, 0.0f};

    int jstart = 0;
    {
        float thr = (float)i0 - span - 96.0f;
        if (thr > 0.0f) jstart = ((int)thr / 64) * 64;
    }

    const int irow[2] = {i0 + R + g, i0 + R + g + 8};

    for (int j0 = jstart; j0 <= i0 + BQ - 64; j0 += 64) {
        __syncthreads();
        {
            int key = tid >> 2, db = (tid & 3) * 16;
            const float* kp = &qkv[(size_t)(b * TT + j0 + key) * C3 + CC + h * 64 + db];
            const float* vp = kp + CC;
            int kswz = (key & 1) | ((key & 2) << 1);
            int pk = ((key & 7) << 3) | (key >> 3);
#pragma unroll
            for (int u = 0; u < 4; u++) {
                float4 kv = *(const float4*)&kp[u * 4];
                float4 vv = *(const float4*)&vp[u * 4];
                float ka[4] = {kv.x, kv.y, kv.z, kv.w};
                float va[4] = {vv.x, vv.y, vv.z, vv.w};
#pragma unroll
                for (int c = 0; c < 4; c++) {
                    int d = db + u * 4 + c;
                    int dswz = (d & 1) | ((d & 2) << 1);
                    int physK = ((((pk >> 2) ^ dswz) << 2) | (pk & 3));
                    Ks[d * 64 + physK] = f2tf32f(ka[c]);
                    int pd = ((d & 7) << 3) | (d >> 3);
                    int physV = ((((pd >> 2) ^ kswz) << 2) | (pd & 3));
                    Vs[key * 64 + physV] = f2tf32f(va[c]);
                }
            }
        }
        __syncthreads();

        float S[8][4];
#pragma unroll
        for (int a = 0; a < 8; a++)
#pragma unroll
            for (int c = 0; c < 4; c++) S[a][c] = 0.0f;
#pragma unroll
        for (int ks = 0; ks < 8; ks++) {
            int r0 = (8 * ks + tig) * 64, r1 = (8 * ks + tig + 4) * 64;
            float4 p0 = *(const float4*)&Ks[r0 + (((2 * g) ^ fswz) << 2)];
            float4 p1 = *(const float4*)&Ks[r0 + (((2 * g + 1) ^ fswz) << 2)];
            float4 q0 = *(const float4*)&Ks[r1 + (((2 * g) ^ fswz) << 2)];
            float4 q1 = *(const float4*)&Ks[r1 + (((2 * g + 1) ^ fswz) << 2)];
            unsigned b0[8], b1[8];
            b0[0] = __float_as_uint(p0.x); b0[1] = __float_as_uint(p0.y);
            b0[2] = __float_as_uint(p0.z); b0[3] = __float_as_uint(p0.w);
            b0[4] = __float_as_uint(p1.x); b0[5] = __float_as_uint(p1.y);
            b0[6] = __float_as_uint(p1.z); b0[7] = __float_as_uint(p1.w);
            b1[0] = __float_as_uint(q0.x); b1[1] = __float_as_uint(q0.y);
            b1[2] = __float_as_uint(q0.z); b1[3] = __float_as_uint(q0.w);
            b1[4] = __float_as_uint(q1.x); b1[5] = __float_as_uint(q1.y);
            b1[6] = __float_as_uint(q1.z); b1[7] = __float_as_uint(q1.w);
#pragma unroll
            for (int a = 0; a < 8; a++)
                mma_tf32(S[a], qf[ks][0], qf[ks][1], qf[ks][2], qf[ks][3],
                         b0[a], b1[a]);
        }

#pragma unroll
        for (int r = 0; r < 2; r++) {
            float tmax = -1e30f;
#pragma unroll
            for (int a = 0; a < 8; a++) {
                tmax = fmaxf(tmax, S[a][2 * r]);
                tmax = fmaxf(tmax, S[a][2 * r + 1]);
            }
            tmax = fmaxf(tmax, __shfl_xor_sync(0xffffffffu, tmax, 1));
            tmax = fmaxf(tmax, __shfl_xor_sync(0xffffffffu, tmax, 2));
            float mnew = fmaxf(mr[r], tmax);
            float corr = fexp2(mr[r] - mnew);
            mr[r] = mnew;
            float rsum = 0.0f;
            int prow = (R + g + 8 * r) * QPSTR;
#pragma unroll
            for (int a = 0; a < 8; a++) {
#pragma unroll
                for (int c = 0; c < 2; c++) {
                    int j = j0 + 8 * a + 2 * tig + c;
                    int rel = irow[r] - j;
                    float p = 0.0f;
                    if (rel >= 0)
                        p = fexp2(S[a][2 * r + c] - mnew) * MT[rel];
                    rsum += p;
                    int p8 = 2 * tig + c;
                    int col = 8 * a + (((p8 & 3) << 1) | (p8 >> 2));
                    QP[prow + col] = f2tf32f(p);
                }
            }
            rsum += __shfl_xor_sync(0xffffffffu, rsum, 1);
            rsum += __shfl_xor_sync(0xffffffffu, rsum, 2);
            lr[r] = lr[r] * corr + rsum;
#pragma unroll
            for (int a = 0; a < 8; a++) {
                O[a][2 * r] *= corr;
                O[a][2 * r + 1] *= corr;
            }
        }
        __syncwarp();

#pragma unroll
        for (int ks = 0; ks < 8; ks++) {
            float2 v0 = *(const float2*)&QP[(R + g) * QPSTR + 8 * ks + 2 * tig];
            float2 v1 = *(const float2*)&QP[(R + g + 8) * QPSTR + 8 * ks + 2 * tig];
            unsigned a0 = __float_as_uint(v0.x), a1 = __float_as_uint(v1.x);
            unsigned a2 = __float_as_uint(v0.y), a3 = __float_as_uint(v1.y);
            int r0 = (8 * ks + tig) * 64, r1 = (8 * ks + tig + 4) * 64;
            float4 p0 = *(const float4*)&Vs[r0 + (((2 * g) ^ fswz) << 2)];
            float4 p1 = *(const float4*)&Vs[r0 + (((2 * g + 1) ^ fswz) << 2)];
            float4 q0 = *(const float4*)&Vs[r1 + (((2 * g) ^ fswz) << 2)];
            float4 q1 = *(const float4*)&Vs[r1 + (((2 * g + 1) ^ fswz) << 2)];
            unsigned b0[8], b1[8];
            b0[0] = __float_as_uint(p0.x); b0[1] = __float_as_uint(p0.y);
            b0[2] = __float_as_uint(p0.z); b0[3] = __float_as_uint(p0.w);
            b0[4] = __float_as_uint(p1.x); b0[5] = __float_as_uint(p1.y);
            b0[6] = __float_as_uint(p1.z); b0[7] = __float_as_uint(p1.w);
            b1[0] = __float_as_uint(q0.x); b1[1] = __float_as_uint(q0.y);
            b1[2] = __float_as_uint(q0.z); b1[3] = __float_as_uint(q0.w);
            b1[4] = __float_as_uint(q1.x); b1[5] = __float_as_uint(q1.y);
            b1[6] = __float_as_uint(q1.z); b1[7] = __float_as_uint(q1.w);
#pragma unroll
            for (int a = 0; a < 8; a++)
                mma_tf32(O[a], a0, a1, a2, a3, b0[a], b1[a]);
        }
    }

    float inv0 = 1.0f / lr[0], inv1 = 1.0f / lr[1];
#pragma unroll
    for (int a = 0; a < 8; a++) {
        int d = 8 * a + 2 * tig;
        float2 o0 = {O[a][0] * inv0, O[a][1] * inv0};
        float2 o1 = {O[a][2] * inv1, O[a][3] * inv1};
        *(float2*)&yout[(size_t)(b * TT + irow[0]) * CC + h * 64 + d] = o0;
        *(float2*)&yout[(size_t)(b * TT + irow[1]) * CC + h * 64 + d] = o1;
    }
}

// ---------------------------------------------------------------------------
__global__ void loss_kernel(const float* __restrict__ sp, const float* __restrict__ pw,
                            const float* __restrict__ rw, float* __restrict__ out,
                            int out_size)
{
    if (threadIdx.x == 0 && blockIdx.x == 0 && out_size > YELEMS) {
        float a = 0.0f;
        for (int h = 0; h < HH; h++) {
            float span   = 2048.0f / (1.0f + expf(-sp[h]));
            float period = 2.0f + 2.0f / (1.0f + expf(-pw[h]));
            float ratio  = -0.25f + 0.5f / (1.0f + expf(-rw[h]));
            float lt = 1.0f / period + 2.0f * ratio - 0.25f + 0.5f;
            a += (span + 32.0f) * lt;
        }
        out[YELEMS] = 2e-6f * a / (float)HH;
    }
}

// ---------------------------------------------------------------------------
extern "C" void kernel_launch(void* const* d_in, const int* in_sizes, int n_in,
                              void* d_out, int out_size)
{
    const float* x       = (const float*)d_in[0];
    const float* w_attn  = (const float*)d_in[1];
    const float* b_attn  = (const float*)d_in[2];
    const float* w_proj  = (const float*)d_in[3];
    const float* b_proj  = (const float*)d_in[4];
    const float* span_p  = (const float*)d_in[5];
    const float* per_w   = (const float*)d_in[6];
    const float* rat_w   = (const float*)d_in[7];
    float* out = (float*)d_out;

    float *qkvp = nullptr, *yattp = nullptr, *maskp = nullptr;
    cudaGetSymbolAddress((void**)&qkvp, g_qkv);
    cudaGetSymbolAddress((void**)&yattp, g_yatt);
    cudaGetSymbolAddress((void**)&maskp, g_mask);

    const int ATTN_SMEM = (BQ * QPSTR + 64 * 64 * 2 + TT) * (int)sizeof(float); // 77824
    cudaFuncSetAttribute(attn_mma, cudaFuncAttributeMaxDynamicSharedMemorySize, ATTN_SMEM);
    cudaFuncSetAttribute(mma_gemm_pipe, cudaFuncAttributeMaxDynamicSharedMemorySize, GEMM_SMEM);

    // 0. mask table
    maskgen<<<HH, 256>>>(span_p, per_w, rat_w, maskp);
    // 1. QKV projection
    mma_gemm_pipe<<<dim3(C3 / 128, MM / 128), 256, GEMM_SMEM>>>(x, w_attn, b_attn, qkvp, MM, C3, CC);
    // 2. attention
    attn_mma<<<dim3(TT / BQ, HH, BB), 256, ATTN_SMEM>>>(qkvp, span_p, maskp, yattp);
    // 3. output projection
    mma_gemm_pipe<<<dim3(CC / 128, MM / 128), 256, GEMM_SMEM>>>(yattp, w_proj, b_proj, out, MM, CC, CC);
    // 4. span loss scalar
    loss_kernel<<<1, 32>>>(span_p, per_w, rat_w, out, out_size);
}

// round 7
// speedup vs baseline: 2.2676x; 2.2676x over previous
#include <cuda_runtime.h>
#include <math.h>

#define BB 2
#define TT 2048
#define CC 1024
#define HH 16
#define DD 64
#define C3 3072
#define MM (BB*TT)          // 4096
#define YELEMS (BB*TT*CC)   // 4194304

#define BQ 128
#define QPSTR 72

// scratch (static device arrays: allocation-free)
__device__ float g_qkv[MM * C3];   // [B*T, 3C]
__device__ float g_yatt[MM * CC];  // [B*T, C]
__device__ float g_mask[HH * TT];  // [H, rel]

__device__ __forceinline__ unsigned f2tf32(float x) {
    unsigned r;
    asm("cvt.rna.tf32.f32 %0, %1;" : "=r"(r) : "f"(x));
    return r;
}
__device__ __forceinline__ float f2tf32f(float x) {
    return __uint_as_float(f2tf32(x));
}

__device__ __forceinline__ void mma_tf32(float c[4], unsigned a0, unsigned a1,
                                         unsigned a2, unsigned a3,
                                         unsigned b0, unsigned b1) {
    asm volatile(
        "mma.sync.aligned.m16n8k8.row.col.f32.tf32.tf32.f32 "
        "{%0,%1,%2,%3}, {%4,%5,%6,%7}, {%8,%9}, {%0,%1,%2,%3};"
        : "+f"(c[0]), "+f"(c[1]), "+f"(c[2]), "+f"(c[3])
        : "r"(a0), "r"(a1), "r"(a2), "r"(a3), "r"(b0), "r"(b1));
}

// FFMA-only exp2 for z <= 0 (clamped at -80). No MUFU.
__device__ __forceinline__ float fexp2(float z) {
    z = fmaxf(z, -80.0f);
    float r = z + 12582912.0f;
    int zi = __float_as_int(r) - 0x4B400000;
    float f = z - (r - 12582912.0f);
    float p = 1.3333558e-3f;
    p = fmaf(p, f, 9.6181291e-3f);
    p = fmaf(p, f, 5.5504109e-2f);
    p = fmaf(p, f, 2.4022651e-1f);
    p = fmaf(p, f, 6.9314718e-1f);
    p = fmaf(p, f, 1.0f);
    return __int_as_float(__float_as_int(p) + (zi << 23));
}

// ---------------------------------------------------------------------------
// tf32 tensor-core GEMM with bias — exact R4 structure (best measured), with
// __launch_bounds__(256, 2): regs capped at 128 -> 2 blocks/SM, so one
// block's LDG phase overlaps the other's MMA phase.
// ---------------------------------------------------------------------------
#define ASTR 40

__global__ __launch_bounds__(256, 2) void mma_gemm_bias(
    const float* __restrict__ A, const float* __restrict__ W,
    const float* __restrict__ bias, float* __restrict__ out,
    int M, int N, int K)
{
    __shared__ float As[128 * ASTR];
    __shared__ float Bs[32 * 128];

    const int tid = threadIdx.x;
    const int m0 = blockIdx.y * 128, n0 = blockIdx.x * 128;
    const int lane = tid & 31, w = tid >> 5;
    const int wM = w >> 1, wN = w & 1;
    const int g = lane >> 2, tig = lane & 3;

    const int arow = tid >> 1, ac0 = (tid & 1) * 16;
    const int brow = tid >> 3, bc0 = (tid & 7) * 16;
    const int bswz = (brow & 1) | ((brow & 2) << 1);

    float acc[2][8][4];
#pragma unroll
    for (int i = 0; i < 2; i++)
#pragma unroll
        for (int j = 0; j < 8; j++)
#pragma unroll
            for (int c = 0; c < 4; c++) acc[i][j][c] = 0.0f;

    const int fswz = (tig & 1) | ((tig & 2) << 1);

    for (int k0 = 0; k0 < K; k0 += 32) {
        {
            const float* ap = &A[(size_t)(m0 + arow) * K + k0 + ac0];
            const float* bp = &W[(size_t)(k0 + brow) * N + n0 + bc0];
            float4 av0 = *(const float4*)&ap[0];
            float4 av1 = *(const float4*)&ap[4];
            float4 av2 = *(const float4*)&ap[8];
            float4 av3 = *(const float4*)&ap[12];
            float4 bv0 = *(const float4*)&bp[0];
            float4 bv1 = *(const float4*)&bp[4];
            float4 bv2 = *(const float4*)&bp[8];
            float4 bv3 = *(const float4*)&bp[12];
            __syncthreads();
            float avv[16] = {av0.x, av0.y, av0.z, av0.w, av1.x, av1.y, av1.z, av1.w,
                             av2.x, av2.y, av2.z, av2.w, av3.x, av3.y, av3.z, av3.w};
            float bvv[16] = {bv0.x, bv0.y, bv0.z, bv0.w, bv1.x, bv1.y, bv1.z, bv1.w,
                             bv2.x, bv2.y, bv2.z, bv2.w, bv3.x, bv3.y, bv3.z, bv3.w};
#pragma unroll
            for (int c = 0; c < 16; c++) {
                int k = ac0 + c;
                int p8 = k & 7;
                int col = (k & ~7) | (((p8 & 3) << 1) | (p8 >> 2));
                As[arow * ASTR + col] = f2tf32f(avv[c]);
            }
#pragma unroll
            for (int c = 0; c < 16; c++) {
                int n = bc0 + c;
                int col = (n & 64) + (n & 7) * 8 + ((n >> 3) & 7);
                int phys = ((col >> 2) ^ bswz) * 4 + (col & 3);
                Bs[brow * 128 + phys] = f2tf32f(bvv[c]);
            }
        }
        __syncthreads();

#pragma unroll
        for (int ka = 0; ka < 4; ka++) {
            unsigned a[2][4];
#pragma unroll
            for (int i = 0; i < 2; i++) {
                int r = wM * 32 + i * 16 + g;
                float2 v0 = *(const float2*)&As[r * ASTR + ka * 8 + 2 * tig];
                float2 v1 = *(const float2*)&As[(r + 8) * ASTR + ka * 8 + 2 * tig];
                a[i][0] = __float_as_uint(v0.x);
                a[i][1] = __float_as_uint(v1.x);
                a[i][2] = __float_as_uint(v0.y);
                a[i][3] = __float_as_uint(v1.y);
            }
            unsigned b0[8], b1[8];
            {
                int chunk = 16 * wN + 2 * g;
                int r0 = (ka * 8 + tig) * 128;
                int r1 = (ka * 8 + tig + 4) * 128;
                float4 p0 = *(const float4*)&Bs[r0 + ((chunk ^ fswz) << 2)];
                float4 p1 = *(const float4*)&Bs[r0 + (((chunk + 1) ^ fswz) << 2)];
                float4 q0 = *(const float4*)&Bs[r1 + ((chunk ^ fswz) << 2)];
                float4 q1 = *(const float4*)&Bs[r1 + (((chunk + 1) ^ fswz) << 2)];
                b0[0] = __float_as_uint(p0.x); b0[1] = __float_as_uint(p0.y);
                b0[2] = __float_as_uint(p0.z); b0[3] = __float_as_uint(p0.w);
                b0[4] = __float_as_uint(p1.x); b0[5] = __float_as_uint(p1.y);
                b0[6] = __float_as_uint(p1.z); b0[7] = __float_as_uint(p1.w);
                b1[0] = __float_as_uint(q0.x); b1[1] = __float_as_uint(q0.y);
                b1[2] = __float_as_uint(q0.z); b1[3] = __float_as_uint(q0.w);
                b1[4] = __float_as_uint(q1.x); b1[5] = __float_as_uint(q1.y);
                b1[6] = __float_as_uint(q1.z); b1[7] = __float_as_uint(q1.w);
            }
#pragma unroll
            for (int i = 0; i < 2; i++)
#pragma unroll
                for (int j = 0; j < 8; j++)
                    mma_tf32(acc[i][j], a[i][0], a[i][1], a[i][2], a[i][3],
                             b0[j], b1[j]);
        }
    }

#pragma unroll
    for (int i = 0; i < 2; i++) {
#pragma unroll
        for (int j = 0; j < 8; j++) {
            int row = m0 + wM * 32 + i * 16 + g;
            int col = n0 + wN * 64 + j * 8 + 2 * tig;
            float bx = bias[col], by = bias[col + 1];
            float2 o0 = {acc[i][j][0] + bx, acc[i][j][1] + by};
            float2 o1 = {acc[i][j][2] + bx, acc[i][j][3] + by};
            *(float2*)&out[(size_t)row * N + col] = o0;
            *(float2*)&out[(size_t)(row + 8) * N + col] = o1;
        }
    }
}

// ---------------------------------------------------------------------------
// mask table: g_mask[h][rel] = mpos(rel)*wave(rel)  (rel >= 0)
// ---------------------------------------------------------------------------
__global__ void maskgen(const float* __restrict__ sp, const float* __restrict__ pw,
                        const float* __restrict__ rw, float* __restrict__ mask)
{
    int h = blockIdx.x;
    float span   = 2048.0f / (1.0f + __expf(-sp[h]));
    float period = 2.0f + 2.0f / (1.0f + __expf(-pw[h]));
    float ratio  = -0.25f + 0.5f / (1.0f + __expf(-rw[h]));
    float amp = period * 0.25f, offs = period * ratio;
    for (int rel = threadIdx.x; rel < TT; rel += blockDim.x) {
        float relf = (float)rel;
        float mpos = fminf(fmaxf((32.0f - relf + span) * 0.03125f, 0.0f), 1.0f);
        float wave = 0.5f * (cosf(6.283185307179586f * relf / period) + 1.0f) * amp
                     + 0.5f + offs;
        wave = fminf(fmaxf(wave, 0.0f), 1.0f);
        mask[h * TT + rel] = mpos * wave;
    }
}

// ---------------------------------------------------------------------------
// Tensor-core flash attention (unchanged from R4, known-good).
// ---------------------------------------------------------------------------
__global__ __launch_bounds__(256) void attn_mma(
    const float* __restrict__ qkv, const float* __restrict__ span_p,
    const float* __restrict__ gmask, float* __restrict__ yout)
{
    extern __shared__ float sm[];
    float* QP = sm;                    // 128 x 72 (Q staging, then P)
    float* Ks = sm + BQ * QPSTR;       // 64 x 64
    float* Vs = Ks + 64 * 64;          // 64 x 64
    float* MT = Vs + 64 * 64;          // 2048 mask entries

    const int tid = threadIdx.x, lane = tid & 31, w = tid >> 5;
    const int g = lane >> 2, tig = lane & 3;
    const int i0 = ((int)gridDim.x - 1 - (int)blockIdx.x) * BQ;
    const int h = blockIdx.y, b = blockIdx.z;
    const int R = w * 16;
    const int fswz = (tig & 1) | ((tig & 2) << 1);

    for (int t = tid; t < TT; t += 256) MT[t] = gmask[h * TT + t];

    const float span = 2048.0f / (1.0f + __expf(-span_p[h]));

    {
        const float SC = 0.125f * 1.4426950408889634f;
        int row = tid >> 1, cb = (tid & 1) * 32;
        const float* src = &qkv[(size_t)(b * TT + i0 + row) * C3 + h * 64 + cb];
#pragma unroll
        for (int u = 0; u < 8; u++) {
            float4 v = *(const float4*)&src[u * 4];
            float vv[4] = {v.x, v.y, v.z, v.w};
#pragma unroll
            for (int c = 0; c < 4; c++) {
                int k = cb + u * 4 + c;
                int p8 = k & 7;
                int col = (k & ~7) | (((p8 & 3) << 1) | (p8 >> 2));
                QP[row * QPSTR + col] = f2tf32f(vv[c] * SC);
            }
        }
    }
    __syncthreads();

    unsigned qf[8][4];
#pragma unroll
    for (int ks = 0; ks < 8; ks++) {
        float2 v0 = *(const float2*)&QP[(R + g) * QPSTR + 8 * ks + 2 * tig];
        float2 v1 = *(const float2*)&QP[(R + g + 8) * QPSTR + 8 * ks + 2 * tig];
        qf[ks][0] = __float_as_uint(v0.x);
        qf[ks][1] = __float_as_uint(v1.x);
        qf[ks][2] = __float_as_uint(v0.y);
        qf[ks][3] = __float_as_uint(v1.y);
    }

    float O[8][4];
#pragma unroll
    for (int a = 0; a < 8; a++)
#pragma unroll
        for (int c = 0; c < 4; c++) O[a][c] = 0.0f;
    float mr[2] = {-1e30f, -1e30f}, lr[2] = {0.0f, 0.0f};

    int jstart = 0;
    {
        float thr = (float)i0 - span - 96.0f;
        if (thr > 0.0f) jstart = ((int)thr / 64) * 64;
    }

    const int irow[2] = {i0 + R + g, i0 + R + g + 8};

    for (int j0 = jstart; j0 <= i0 + BQ - 64; j0 += 64) {
        __syncthreads();
        {
            int key = tid >> 2, db = (tid & 3) * 16;
            const float* kp = &qkv[(size_t)(b * TT + j0 + key) * C3 + CC + h * 64 + db];
            const float* vp = kp + CC;
            int kswz = (key & 1) | ((key & 2) << 1);
            int pk = ((key & 7) << 3) | (key >> 3);
#pragma unroll
            for (int u = 0; u < 4; u++) {
                float4 kv = *(const float4*)&kp[u * 4];
                float4 vv = *(const float4*)&vp[u * 4];
                float ka[4] = {kv.x, kv.y, kv.z, kv.w};
                float va[4] = {vv.x, vv.y, vv.z, vv.w};
#pragma unroll
                for (int c = 0; c < 4; c++) {
                    int d = db + u * 4 + c;
                    int dswz = (d & 1) | ((d & 2) << 1);
                    int physK = ((((pk >> 2) ^ dswz) << 2) | (pk & 3));
                    Ks[d * 64 + physK] = f2tf32f(ka[c]);
                    int pd = ((d & 7) << 3) | (d >> 3);
                    int physV = ((((pd >> 2) ^ kswz) << 2) | (pd & 3));
                    Vs[key * 64 + physV] = f2tf32f(va[c]);
                }
            }
        }
        __syncthreads();

        float S[8][4];
#pragma unroll
        for (int a = 0; a < 8; a++)
#pragma unroll
            for (int c = 0; c < 4; c++) S[a][c] = 0.0f;
#pragma unroll
        for (int ks = 0; ks < 8; ks++) {
            int r0 = (8 * ks + tig) * 64, r1 = (8 * ks + tig + 4) * 64;
            float4 p0 = *(const float4*)&Ks[r0 + (((2 * g) ^ fswz) << 2)];
            float4 p1 = *(const float4*)&Ks[r0 + (((2 * g + 1) ^ fswz) << 2)];
            float4 q0 = *(const float4*)&Ks[r1 + (((2 * g) ^ fswz) << 2)];
            float4 q1 = *(const float4*)&Ks[r1 + (((2 * g + 1) ^ fswz) << 2)];
            unsigned b0[8], b1[8];
            b0[0] = __float_as_uint(p0.x); b0[1] = __float_as_uint(p0.y);
            b0[2] = __float_as_uint(p0.z); b0[3] = __float_as_uint(p0.w);
            b0[4] = __float_as_uint(p1.x); b0[5] = __float_as_uint(p1.y);
            b0[6] = __float_as_uint(p1.z); b0[7] = __float_as_uint(p1.w);
            b1[0] = __float_as_uint(q0.x); b1[1] = __float_as_uint(q0.y);
            b1[2] = __float_as_uint(q0.z); b1[3] = __float_as_uint(q0.w);
            b1[4] = __float_as_uint(q1.x); b1[5] = __float_as_uint(q1.y);
            b1[6] = __float_as_uint(q1.z); b1[7] = __float_as_uint(q1.w);
#pragma unroll
            for (int a = 0; a < 8; a++)
                mma_tf32(S[a], qf[ks][0], qf[ks][1], qf[ks][2], qf[ks][3],
                         b0[a], b1[a]);
        }

#pragma unroll
        for (int r = 0; r < 2; r++) {
            float tmax = -1e30f;
#pragma unroll
            for (int a = 0; a < 8; a++) {
                tmax = fmaxf(tmax, S[a][2 * r]);
                tmax = fmaxf(tmax, S[a][2 * r + 1]);
            }
            tmax = fmaxf(tmax, __shfl_xor_sync(0xffffffffu, tmax, 1));
            tmax = fmaxf(tmax, __shfl_xor_sync(0xffffffffu, tmax, 2));
            float mnew = fmaxf(mr[r], tmax);
            float corr = fexp2(mr[r] - mnew);
            mr[r] = mnew;
            float rsum = 0.0f;
            int prow = (R + g + 8 * r) * QPSTR;
#pragma unroll
            for (int a = 0; a < 8; a++) {
#pragma unroll
                for (int c = 0; c < 2; c++) {
                    int j = j0 + 8 * a + 2 * tig + c;
                    int rel = irow[r] - j;
                    float p = 0.0f;
                    if (rel >= 0)
                        p = fexp2(S[a][2 * r + c] - mnew) * MT[rel];
                    rsum += p;
                    int p8 = 2 * tig + c;
                    int col = 8 * a + (((p8 & 3) << 1) | (p8 >> 2));
                    QP[prow + col] = f2tf32f(p);
                }
            }
            rsum += __shfl_xor_sync(0xffffffffu, rsum, 1);
            rsum += __shfl_xor_sync(0xffffffffu, rsum, 2);
            lr[r] = lr[r] * corr + rsum;
#pragma unroll
            for (int a = 0; a < 8; a++) {
                O[a][2 * r] *= corr;
                O[a][2 * r + 1] *= corr;
            }
        }
        __syncwarp();

#pragma unroll
        for (int ks = 0; ks < 8; ks++) {
            float2 v0 = *(const float2*)&QP[(R + g) * QPSTR + 8 * ks + 2 * tig];
            float2 v1 = *(const float2*)&QP[(R + g + 8) * QPSTR + 8 * ks + 2 * tig];
            unsigned a0 = __float_as_uint(v0.x), a1 = __float_as_uint(v1.x);
            unsigned a2 = __float_as_uint(v0.y), a3 = __float_as_uint(v1.y);
            int r0 = (8 * ks + tig) * 64, r1 = (8 * ks + tig + 4) * 64;
            float4 p0 = *(const float4*)&Vs[r0 + (((2 * g) ^ fswz) << 2)];
            float4 p1 = *(const float4*)&Vs[r0 + (((2 * g + 1) ^ fswz) << 2)];
            float4 q0 = *(const float4*)&Vs[r1 + (((2 * g) ^ fswz) << 2)];
            float4 q1 = *(const float4*)&Vs[r1 + (((2 * g + 1) ^ fswz) << 2)];
            unsigned b0[8], b1[8];
            b0[0] = __float_as_uint(p0.x); b0[1] = __float_as_uint(p0.y);
            b0[2] = __float_as_uint(p0.z); b0[3] = __float_as_uint(p0.w);
            b0[4] = __float_as_uint(p1.x); b0[5] = __float_as_uint(p1.y);
            b0[6] = __float_as_uint(p1.z); b0[7] = __float_as_uint(p1.w);
            b1[0] = __float_as_uint(q0.x); b1[1] = __float_as_uint(q0.y);
            b1[2] = __float_as_uint(q0.z); b1[3] = __float_as_uint(q0.w);
            b1[4] = __float_as_uint(q1.x); b1[5] = __float_as_uint(q1.y);
            b1[6] = __float_as_uint(q1.z); b1[7] = __float_as_uint(q1.w);
#pragma unroll
            for (int a = 0; a < 8; a++)
                mma_tf32(O[a], a0, a1, a2, a3, b0[a], b1[a]);
        }
    }

    float inv0 = 1.0f / lr[0], inv1 = 1.0f / lr[1];
#pragma unroll
    for (int a = 0; a < 8; a++) {
        int d = 8 * a + 2 * tig;
        float2 o0 = {O[a][0] * inv0, O[a][1] * inv0};
        float2 o1 = {O[a][2] * inv1, O[a][3] * inv1};
        *(float2*)&yout[(size_t)(b * TT + irow[0]) * CC + h * 64 + d] = o0;
        *(float2*)&yout[(size_t)(b * TT + irow[1]) * CC + h * 64 + d] = o1;
    }
}

// ---------------------------------------------------------------------------
__global__ void loss_kernel(const float* __restrict__ sp, const float* __restrict__ pw,
                            const float* __restrict__ rw, float* __restrict__ out,
                            int out_size)
{
    if (threadIdx.x == 0 && blockIdx.x == 0 && out_size > YELEMS) {
        float a = 0.0f;
        for (int h = 0; h < HH; h++) {
            float span   = 2048.0f / (1.0f + expf(-sp[h]));
            float period = 2.0f + 2.0f / (1.0f + expf(-pw[h]));
            float ratio  = -0.25f + 0.5f / (1.0f + expf(-rw[h]));
            float lt = 1.0f / period + 2.0f * ratio - 0.25f + 0.5f;
            a += (span + 32.0f) * lt;
        }
        out[YELEMS] = 2e-6f * a / (float)HH;
    }
}

// ---------------------------------------------------------------------------
extern "C" void kernel_launch(void* const* d_in, const int* in_sizes, int n_in,
                              void* d_out, int out_size)
{
    const float* x       = (const float*)d_in[0];
    const float* w_attn  = (const float*)d_in[1];
    const float* b_attn  = (const float*)d_in[2];
    const float* w_proj  = (const float*)d_in[3];
    const float* b_proj  = (const float*)d_in[4];
    const float* span_p  = (const float*)d_in[5];
    const float* per_w   = (const float*)d_in[6];
    const float* rat_w   = (const float*)d_in[7];
    float* out = (float*)d_out;

    float *qkvp = nullptr, *yattp = nullptr, *maskp = nullptr;
    cudaGetSymbolAddress((void**)&qkvp, g_qkv);
    cudaGetSymbolAddress((void**)&yattp, g_yatt);
    cudaGetSymbolAddress((void**)&maskp, g_mask);

    const int ATTN_SMEM = (BQ * QPSTR + 64 * 64 * 2 + TT) * (int)sizeof(float); // 77824
    cudaFuncSetAttribute(attn_mma, cudaFuncAttributeMaxDynamicSharedMemorySize, ATTN_SMEM);

    // 0. mask table
    maskgen<<<HH, 256>>>(span_p, per_w, rat_w, maskp);
    // 1. QKV projection
    mma_gemm_bias<<<dim3(C3 / 128, MM / 128), 256>>>(x, w_attn, b_attn, qkvp, MM, C3, CC);
    // 2. attention
    attn_mma<<<dim3(TT / BQ, HH, BB), 256, ATTN_SMEM>>>(qkvp, span_p, maskp, yattp);
    // 3. output projection
    mma_gemm_bias<<<dim3(CC / 128, MM / 128), 256>>>(yattp, w_proj, b_proj, out, MM, CC, CC);
    // 4. span loss scalar
    loss_kernel<<<1, 32>>>(span_p, per_w, rat_w, out, out_size);
}

// round 10
// speedup vs baseline: 3.1193x; 1.3756x over previous
#include <cuda_runtime.h>
#include <math.h>

#define BB 2
#define TT 2048
#define CC 1024
#define HH 16
#define C3 3072
#define MM (BB*TT)          // 4096
#define YELEMS (BB*TT*CC)   // 4194304

#define BQ 128
#define QPSTR 72

// scratch (static device arrays: allocation-free)
__device__ float g_qkv[MM * C3];   // [B*T, 3C]  (n within-8 perm3'd)
__device__ float g_yatt[MM * CC];  // [B*T, C]   (cols perm3'd = proj A layout, tf32-rounded)
__device__ float g_mask[HH * TT];  // [H, rel]
__device__ float g_x[MM * CC];     // x, k-perm3'd, tf32-rounded
__device__ float g_wa[CC * C3];    // w_attn, n B-permuted, tf32-rounded
__device__ float g_wp[CC * CC];    // w_proj, n B-permuted, tf32-rounded

__device__ __forceinline__ int perm3d(int p) { return ((p & 3) << 1) | (p >> 2); }

__device__ __forceinline__ unsigned f2tf32(float x) {
    unsigned r;
    asm("cvt.rna.tf32.f32 %0, %1;" : "=r"(r) : "f"(x));
    return r;
}
__device__ __forceinline__ float f2tf32f(float x) {
    return __uint_as_float(f2tf32(x));
}

__device__ __forceinline__ void mma_tf32(float c[4], unsigned a0, unsigned a1,
                                         unsigned a2, unsigned a3,
                                         unsigned b0, unsigned b1) {
    asm volatile(
        "mma.sync.aligned.m16n8k8.row.col.f32.tf32.tf32.f32 "
        "{%0,%1,%2,%3}, {%4,%5,%6,%7}, {%8,%9}, {%0,%1,%2,%3};"
        : "+f"(c[0]), "+f"(c[1]), "+f"(c[2]), "+f"(c[3])
        : "r"(a0), "r"(a1), "r"(a2), "r"(a3), "r"(b0), "r"(b1));
}

// FFMA-only exp2 for z <= 0 (clamped at -80). No MUFU.
__device__ __forceinline__ float fexp2(float z) {
    z = fmaxf(z, -80.0f);
    float r = z + 12582912.0f;
    int zi = __float_as_int(r) - 0x4B400000;
    float f = z - (r - 12582912.0f);
    float p = 1.3333558e-3f;
    p = fmaf(p, f, 9.6181291e-3f);
    p = fmaf(p, f, 5.5504109e-2f);
    p = fmaf(p, f, 2.4022651e-1f);
    p = fmaf(p, f, 6.9314718e-1f);
    p = fmaf(p, f, 1.0f);
    return __int_as_float(__float_as_int(p) + (zi << 23));
}

#define CP16(dst, src) \
    asm volatile("cp.async.cg.shared.global [%0], [%1], 16;" :: "r"(dst), "l"(src))
#define CP_COMMIT() asm volatile("cp.async.commit_group;" ::: "memory")
#define CP_WAIT2()  asm volatile("cp.async.wait_group 2;" ::: "memory")

// ---------------------------------------------------------------------------
// pre-permute kernels (now also tf32-round so cp.async carries exact tf32;
// HW truncation in mma.tf32 is then lossless -> no truncation bias)
// ---------------------------------------------------------------------------
// A-side: within-8 k interleave: pos = (k&~7)|perm3(k&7). out8 = {0,4,1,5,2,6,3,7}
__global__ void permA(const float* __restrict__ in, float* __restrict__ out, int total8)
{
    int idx = blockIdx.x * blockDim.x + threadIdx.x;
    if (idx >= total8) return;
    const float4* s = (const float4*)(in + (size_t)idx * 8);
    float4 v0 = s[0], v1 = s[1];
    float4 o0 = {f2tf32f(v0.x), f2tf32f(v1.x), f2tf32f(v0.y), f2tf32f(v1.y)};
    float4 o1 = {f2tf32f(v0.z), f2tf32f(v1.z), f2tf32f(v0.w), f2tf32f(v1.w)};
    float4* d = (float4*)(out + (size_t)idx * 8);
    d[0] = o0; d[1] = o1;
}

// B-side: per-64 n-block transpose: out[p] = in[(p&~63) + ((p&7)<<3) + ((p>>3)&7)]
__global__ void permW(const float* __restrict__ in, float* __restrict__ out, int K, int N)
{
    int idx = blockIdx.x * blockDim.x + threadIdx.x;
    int total4 = K * (N >> 2);
    if (idx >= total4) return;
    int nq = idx % (N >> 2);
    int k  = idx / (N >> 2);
    int np = nq * 4;
    int blk = np & ~127;
    int p = np & 127;
    int hi = p & 64;
    int nlow = (p >> 3) & 7;
    int e0 = p & 7;
    const float* row = in + (size_t)k * N + blk;
    float4 o;
    o.x = f2tf32f(row[hi + ((e0 + 0) << 3) + nlow]);
    o.y = f2tf32f(row[hi + ((e0 + 1) << 3) + nlow]);
    o.z = f2tf32f(row[hi + ((e0 + 2) << 3) + nlow]);
    o.w = f2tf32f(row[hi + ((e0 + 3) << 3) + nlow]);
    *(float4*)(out + (size_t)k * N + np) = o;
}

// ---------------------------------------------------------------------------
// cp.async 4-stage tf32 GEMM: out[M,N] = A@W + bias. A pre-perm3'd (k), W
// pre-B-permuted (n), both pre-tf32-rounded. Block 128x256, warp tile 64x64
// (2x4 grid), K-step 32.
// A smem [128][32], chunk swizzle phys = c ^ (row&7).
// B smem [32][256],  phys = (c&~7)|((c^(row&7))&7).
// permOut=1: scatter within-8 perm3 over n (for qkv -> attention chain).
// ---------------------------------------------------------------------------
#define KS 32
#define ASTGF (128 * 32)
#define BSTGF (32 * 256)
#define NSTG 4
#define GEMM_SMEM ((NSTG * (ASTGF + BSTGF)) * 4)   // 196608 bytes

__device__ __forceinline__ void gemm_copy_stage(
    unsigned abase, unsigned bbase,
    const float* __restrict__ A, const float* __restrict__ W,
    int m0, int n0, int k0, int K, int N, int tid)
{
    const int r8 = tid >> 3, c8 = tid & 7;
#pragma unroll
    for (int u = 0; u < 4; u++) {
        int row = r8 + 32 * u;
        int phys = c8 ^ (row & 7);
        unsigned dst = abase + (unsigned)(row * 32 + phys * 4) * 4u;
        const float* src = A + (size_t)(m0 + row) * K + k0 + c8 * 4;
        CP16(dst, src);
    }
#pragma unroll
    for (int u = 0; u < 8; u++) {
        int c = c8 + 8 * u;
        int phys = (c & ~7) | ((c ^ (r8 & 7)) & 7);
        unsigned dst = bbase + (unsigned)(r8 * 256 + phys * 4) * 4u;
        const float* src = W + (size_t)(k0 + r8) * N + n0 + c * 4;
        CP16(dst, src);
    }
    CP_COMMIT();
}

__global__ __launch_bounds__(256, 1) void gemm_cp(
    const float* __restrict__ A, const float* __restrict__ W,
    const float* __restrict__ bias, float* __restrict__ out,
    int M, int N, int K, int permOut)
{
    extern __shared__ float gs[];
    float* Asm = gs;
    float* Bsm = gs + NSTG * ASTGF;
    unsigned abase0 = (unsigned)__cvta_generic_to_shared(Asm);
    unsigned bbase0 = (unsigned)__cvta_generic_to_shared(Bsm);

    const int tid = threadIdx.x, lane = tid & 31, w = tid >> 5;
    const int wM = w >> 2, wN = w & 3;
    const int g = lane >> 2, tig = lane & 3;
    const int m0 = blockIdx.y * 128, n0 = blockIdx.x * 256;
    const int NIT = K / KS;

    float acc[4][8][4];
#pragma unroll
    for (int i = 0; i < 4; i++)
#pragma unroll
        for (int j = 0; j < 8; j++)
#pragma unroll
            for (int c = 0; c < 4; c++) acc[i][j][c] = 0.0f;

    // prologue: stages 0..NSTG-2
#pragma unroll
    for (int s = 0; s < NSTG - 1; s++)
        gemm_copy_stage(abase0 + s * ASTGF * 4, bbase0 + s * BSTGF * 4,
                        A, W, m0, n0, s * KS, K, N, tid);

    for (int it = 0; it < NIT; it++) {
        CP_WAIT2();
        __syncthreads();

        const float* as = Asm + (it & (NSTG - 1)) * ASTGF;
        const float* bs = Bsm + (it & (NSTG - 1)) * BSTGF;

#pragma unroll
        for (int ka = 0; ka < 4; ka++) {
            unsigned a[4][4];
            {
                int c0 = 2 * ka + (tig >> 1);
                int aoff = (tig & 1) * 2;
                int physA = (c0 ^ g) * 4 + aoff;
#pragma unroll
                for (int i = 0; i < 4; i++) {
                    int R = wM * 64 + i * 16 + g;
                    float2 v0 = *(const float2*)&as[R * 32 + physA];
                    float2 v1 = *(const float2*)&as[(R + 8) * 32 + physA];
                    a[i][0] = __float_as_uint(v0.x);
                    a[i][1] = __float_as_uint(v1.x);
                    a[i][2] = __float_as_uint(v0.y);
                    a[i][3] = __float_as_uint(v1.y);
                }
            }
            unsigned b0[8], b1[8];
            {
                int cb = wN * 16 + 2 * g;
                int kr0 = 8 * ka + tig, kr1 = kr0 + 4;
                int t0 = tig, t1 = (tig + 4) & 7;
                float4 p0 = *(const float4*)&bs[kr0 * 256 + ((cb & ~7) | ((cb ^ t0) & 7)) * 4];
                float4 p1 = *(const float4*)&bs[kr0 * 256 + (((cb + 1) & ~7) | (((cb + 1) ^ t0) & 7)) * 4];
                float4 q0 = *(const float4*)&bs[kr1 * 256 + ((cb & ~7) | ((cb ^ t1) & 7)) * 4];
                float4 q1 = *(const float4*)&bs[kr1 * 256 + (((cb + 1) & ~7) | (((cb + 1) ^ t1) & 7)) * 4];
                b0[0] = __float_as_uint(p0.x); b0[1] = __float_as_uint(p0.y);
                b0[2] = __float_as_uint(p0.z); b0[3] = __float_as_uint(p0.w);
                b0[4] = __float_as_uint(p1.x); b0[5] = __float_as_uint(p1.y);
                b0[6] = __float_as_uint(p1.z); b0[7] = __float_as_uint(p1.w);
                b1[0] = __float_as_uint(q0.x); b1[1] = __float_as_uint(q0.y);
                b1[2] = __float_as_uint(q0.z); b1[3] = __float_as_uint(q0.w);
                b1[4] = __float_as_uint(q1.x); b1[5] = __float_as_uint(q1.y);
                b1[6] = __float_as_uint(q1.z); b1[7] = __float_as_uint(q1.w);
            }
#pragma unroll
            for (int i = 0; i < 4; i++)
#pragma unroll
                for (int j = 0; j < 8; j++)
                    mma_tf32(acc[i][j], a[i][0], a[i][1], a[i][2], a[i][3],
                             b0[j], b1[j]);
        }

        // tail: issue stage it+NSTG-1 (or empty commit to keep group count)
        int nxt = it + NSTG - 1;
        if (nxt < NIT) {
            int s = nxt & (NSTG - 1);
            gemm_copy_stage(abase0 + s * ASTGF * 4, bbase0 + s * BSTGF * 4,
                            A, W, m0, n0, nxt * KS, K, N, tid);
        } else {
            CP_COMMIT();
        }
    }

    // epilogue
#pragma unroll
    for (int i = 0; i < 4; i++) {
#pragma unroll
        for (int j = 0; j < 8; j++) {
            int row = m0 + wM * 64 + i * 16 + g;
            int col = n0 + wN * 64 + j * 8 + 2 * tig;
            float bx = bias[col], by = bias[col + 1];
            float v0 = acc[i][j][0] + bx, v1 = acc[i][j][1] + by;
            float v2 = acc[i][j][2] + bx, v3 = acc[i][j][3] + by;
            if (permOut) {
                int p0 = (col & ~7) | perm3d(col & 7);
                int p1 = (col & ~7) | perm3d((col + 1) & 7);
                out[(size_t)row * N + p0] = v0;
                out[(size_t)row * N + p1] = v1;
                out[(size_t)(row + 8) * N + p0] = v2;
                out[(size_t)(row + 8) * N + p1] = v3;
            } else {
                float2 o0 = {v0, v1}, o1 = {v2, v3};
                *(float2*)&out[(size_t)row * N + col] = o0;
                *(float2*)&out[(size_t)(row + 8) * N + col] = o1;
            }
        }
    }
}

// ---------------------------------------------------------------------------
// mask table
// ---------------------------------------------------------------------------
__global__ void maskgen(const float* __restrict__ sp, const float* __restrict__ pw,
                        const float* __restrict__ rw, float* __restrict__ mask)
{
    int h = blockIdx.x;
    float span   = 2048.0f / (1.0f + __expf(-sp[h]));
    float period = 2.0f + 2.0f / (1.0f + __expf(-pw[h]));
    float ratio  = -0.25f + 0.5f / (1.0f + __expf(-rw[h]));
    float amp = period * 0.25f, offs = period * ratio;
    for (int rel = threadIdx.x; rel < TT; rel += blockDim.x) {
        float relf = (float)rel;
        float mpos = fminf(fmaxf((32.0f - relf + span) * 0.03125f, 0.0f), 1.0f);
        float wave = 0.5f * (cosf(6.283185307179586f * relf / period) + 1.0f) * amp
                     + 0.5f + offs;
        wave = fminf(fmaxf(wave, 0.0f), 1.0f);
        mask[h * TT + rel] = mpos * wave;
    }
}

// ---------------------------------------------------------------------------
// Tensor-core flash attention. qkv is n-perm3'd.
// Q staging: straight copy (positions = perm3'd d) -> Q fragment slot tig
//            holds logical d = 8ks+tig.
// K staging: row remapped kr = perm3inv(position) so slot tig also holds
//            logical d = 8ks+tig.
// V staging: by position; O epilogue writes position-space (tf32-rounded)
//            -> y_att lands directly in proj's A (perm3, tf32) layout.
// ---------------------------------------------------------------------------
__global__ __launch_bounds__(256) void attn_mma(
    const float* __restrict__ qkv, const float* __restrict__ span_p,
    const float* __restrict__ gmask, float* __restrict__ yout)
{
    extern __shared__ float sm[];
    float* QP = sm;                    // 128 x 72 (Q staging, then P)
    float* Ks = sm + BQ * QPSTR;       // 64 x 64
    float* Vs = Ks + 64 * 64;          // 64 x 64
    float* MT = Vs + 64 * 64;          // 2048 mask entries

    const int tid = threadIdx.x, lane = tid & 31, w = tid >> 5;
    const int g = lane >> 2, tig = lane & 3;
    const int i0 = ((int)gridDim.x - 1 - (int)blockIdx.x) * BQ;
    const int h = blockIdx.y, b = blockIdx.z;
    const int R = w * 16;
    const int fswz = (tig & 1) | ((tig & 2) << 1);

    for (int t = tid; t < TT; t += 256) MT[t] = gmask[h * TT + t];

    const float span = 2048.0f / (1.0f + __expf(-span_p[h]));

    // stage Q: straight copy (gmem already perm3'd), scaled to log2 domain
    {
        const float SC = 0.125f * 1.4426950408889634f;
        int row = tid >> 1, cb = (tid & 1) * 32;
        const float* src = &qkv[(size_t)(b * TT + i0 + row) * C3 + h * 64 + cb];
#pragma unroll
        for (int u = 0; u < 8; u++) {
            float4 v = *(const float4*)&src[u * 4];
            float4 o = {f2tf32f(v.x * SC), f2tf32f(v.y * SC),
                        f2tf32f(v.z * SC), f2tf32f(v.w * SC)};
            *(float4*)&QP[row * QPSTR + cb + u * 4] = o;
        }
    }
    __syncthreads();

    unsigned qf[8][4];
#pragma unroll
    for (int ks = 0; ks < 8; ks++) {
        float2 v0 = *(const float2*)&QP[(R + g) * QPSTR + 8 * ks + 2 * tig];
        float2 v1 = *(const float2*)&QP[(R + g + 8) * QPSTR + 8 * ks + 2 * tig];
        qf[ks][0] = __float_as_uint(v0.x);
        qf[ks][1] = __float_as_uint(v1.x);
        qf[ks][2] = __float_as_uint(v0.y);
        qf[ks][3] = __float_as_uint(v1.y);
    }

    float O[8][4];
#pragma unroll
    for (int a = 0; a < 8; a++)
#pragma unroll
        for (int c = 0; c < 4; c++) O[a][c] = 0.0f;
    float mr[2] = {-1e30f, -1e30f}, lr[2] = {0.0f, 0.0f};

    int jstart = 0;
    {
        float thr = (float)i0 - span - 96.0f;
        if (thr > 0.0f) jstart = ((int)thr / 64) * 64;
    }

    const int irow[2] = {i0 + R + g, i0 + R + g + 8};

    for (int j0 = jstart; j0 <= i0 + BQ - 64; j0 += 64) {
        __syncthreads();
        {
            int key = tid >> 2, db = (tid & 3) * 16;
            const float* kp = &qkv[(size_t)(b * TT + j0 + key) * C3 + CC + h * 64 + db];
            const float* vp = kp + CC;
            int kswz = (key & 1) | ((key & 2) << 1);
            int pk = ((key & 7) << 3) | (key >> 3);
#pragma unroll
            for (int u = 0; u < 4; u++) {
                float4 kv = *(const float4*)&kp[u * 4];
                float4 vv = *(const float4*)&vp[u * 4];
                float ka[4] = {kv.x, kv.y, kv.z, kv.w};
                float va[4] = {vv.x, vv.y, vv.z, vv.w};
#pragma unroll
                for (int c = 0; c < 4; c++) {
                    int d = db + u * 4 + c;                       // gmem position p
                    // K row remap: kr = (p&~7) | perm3inv(p&7)
                    int kr = (d & ~7) | ((d & 1) << 2) | ((d & 7) >> 1);
                    int dswz = (kr & 1) | ((kr & 2) << 1);
                    int physK = ((((pk >> 2) ^ dswz) << 2) | (pk & 3));
                    Ks[kr * 64 + physK] = f2tf32f(ka[c]);
                    int pd = ((d & 7) << 3) | (d >> 3);
                    int physV = ((((pd >> 2) ^ kswz) << 2) | (pd & 3));
                    Vs[key * 64 + physV] = f2tf32f(va[c]);
                }
            }
        }
        __syncthreads();

        float S[8][4];
#pragma unroll
        for (int a = 0; a < 8; a++)
#pragma unroll
            for (int c = 0; c < 4; c++) S[a][c] = 0.0f;
#pragma unroll
        for (int ks = 0; ks < 8; ks++) {
            int r0 = (8 * ks + tig) * 64, r1 = (8 * ks + tig + 4) * 64;
            float4 p0 = *(const float4*)&Ks[r0 + (((2 * g) ^ fswz) << 2)];
            float4 p1 = *(const float4*)&Ks[r0 + (((2 * g + 1) ^ fswz) << 2)];
            float4 q0 = *(const float4*)&Ks[r1 + (((2 * g) ^ fswz) << 2)];
            float4 q1 = *(const float4*)&Ks[r1 + (((2 * g + 1) ^ fswz) << 2)];
            unsigned b0[8], b1[8];
            b0[0] = __float_as_uint(p0.x); b0[1] = __float_as_uint(p0.y);
            b0[2] = __float_as_uint(p0.z); b0[3] = __float_as_uint(p0.w);
            b0[4] = __float_as_uint(p1.x); b0[5] = __float_as_uint(p1.y);
            b0[6] = __float_as_uint(p1.z); b0[7] = __float_as_uint(p1.w);
            b1[0] = __float_as_uint(q0.x); b1[1] = __float_as_uint(q0.y);
            b1[2] = __float_as_uint(q0.z); b1[3] = __float_as_uint(q0.w);
            b1[4] = __float_as_uint(q1.x); b1[5] = __float_as_uint(q1.y);
            b1[6] = __float_as_uint(q1.z); b1[7] = __float_as_uint(q1.w);
#pragma unroll
            for (int a = 0; a < 8; a++)
                mma_tf32(S[a], qf[ks][0], qf[ks][1], qf[ks][2], qf[ks][3],
                         b0[a], b1[a]);
        }

#pragma unroll
        for (int r = 0; r < 2; r++) {
            float tmax = -1e30f;
#pragma unroll
            for (int a = 0; a < 8; a++) {
                tmax = fmaxf(tmax, S[a][2 * r]);
                tmax = fmaxf(tmax, S[a][2 * r + 1]);
            }
            tmax = fmaxf(tmax, __shfl_xor_sync(0xffffffffu, tmax, 1));
            tmax = fmaxf(tmax, __shfl_xor_sync(0xffffffffu, tmax, 2));
            float mnew = fmaxf(mr[r], tmax);
            float corr = fexp2(mr[r] - mnew);
            mr[r] = mnew;
            float rsum = 0.0f;
            int prow = (R + g + 8 * r) * QPSTR;
#pragma unroll
            for (int a = 0; a < 8; a++) {
#pragma unroll
                for (int c = 0; c < 2; c++) {
                    int j = j0 + 8 * a + 2 * tig + c;
                    int rel = irow[r] - j;
                    float p = 0.0f;
                    if (rel >= 0)
                        p = fexp2(S[a][2 * r + c] - mnew) * MT[rel];
                    rsum += p;
                    int p8 = 2 * tig + c;
                    int col = 8 * a + (((p8 & 3) << 1) | (p8 >> 2));
                    QP[prow + col] = f2tf32f(p);
                }
            }
            rsum += __shfl_xor_sync(0xffffffffu, rsum, 1);
            rsum += __shfl_xor_sync(0xffffffffu, rsum, 2);
            lr[r] = lr[r] * corr + rsum;
#pragma unroll
            for (int a = 0; a < 8; a++) {
                O[a][2 * r] *= corr;
                O[a][2 * r + 1] *= corr;
            }
        }
        __syncwarp();

#pragma unroll
        for (int ks = 0; ks < 8; ks++) {
            float2 v0 = *(const float2*)&QP[(R + g) * QPSTR + 8 * ks + 2 * tig];
            float2 v1 = *(const float2*)&QP[(R + g + 8) * QPSTR + 8 * ks + 2 * tig];
            unsigned a0 = __float_as_uint(v0.x), a1 = __float_as_uint(v1.x);
            unsigned a2 = __float_as_uint(v0.y), a3 = __float_as_uint(v1.y);
            int r0 = (8 * ks + tig) * 64, r1 = (8 * ks + tig + 4) * 64;
            float4 p0 = *(const float4*)&Vs[r0 + (((2 * g) ^ fswz) << 2)];
            float4 p1 = *(const float4*)&Vs[r0 + (((2 * g + 1) ^ fswz) << 2)];
            float4 q0 = *(const float4*)&Vs[r1 + (((2 * g) ^ fswz) << 2)];
            float4 q1 = *(const float4*)&Vs[r1 + (((2 * g + 1) ^ fswz) << 2)];
            unsigned b0[8], b1[8];
            b0[0] = __float_as_uint(p0.x); b0[1] = __float_as_uint(p0.y);
            b0[2] = __float_as_uint(p0.z); b0[3] = __float_as_uint(p0.w);
            b0[4] = __float_as_uint(p1.x); b0[5] = __float_as_uint(p1.y);
            b0[6] = __float_as_uint(p1.z); b0[7] = __float_as_uint(p1.w);
            b1[0] = __float_as_uint(q0.x); b1[1] = __float_as_uint(q0.y);
            b1[2] = __float_as_uint(q0.z); b1[3] = __float_as_uint(q0.w);
            b1[4] = __float_as_uint(q1.x); b1[5] = __float_as_uint(q1.y);
            b1[6] = __float_as_uint(q1.z); b1[7] = __float_as_uint(q1.w);
#pragma unroll
            for (int a = 0; a < 8; a++)
                mma_tf32(O[a], a0, a1, a2, a3, b0[a], b1[a]);
        }
    }

    // epilogue: normalize + tf32-round (y_att feeds proj GEMM's A via cp.async)
    float inv0 = 1.0f / lr[0], inv1 = 1.0f / lr[1];
#pragma unroll
    for (int a = 0; a < 8; a++) {
        int d = 8 * a + 2 * tig;
        float2 o0 = {f2tf32f(O[a][0] * inv0), f2tf32f(O[a][1] * inv0)};
        float2 o1 = {f2tf32f(O[a][2] * inv1), f2tf32f(O[a][3] * inv1)};
        *(float2*)&yout[(size_t)(b * TT + irow[0]) * CC + h * 64 + d] = o0;
        *(float2*)&yout[(size_t)(b * TT + irow[1]) * CC + h * 64 + d] = o1;
    }
}

// ---------------------------------------------------------------------------
__global__ void loss_kernel(const float* __restrict__ sp, const float* __restrict__ pw,
                            const float* __restrict__ rw, float* __restrict__ out,
                            int out_size)
{
    if (threadIdx.x == 0 && blockIdx.x == 0 && out_size > YELEMS) {
        float a = 0.0f;
        for (int h = 0; h < HH; h++) {
            float span   = 2048.0f / (1.0f + expf(-sp[h]));
            float period = 2.0f + 2.0f / (1.0f + expf(-pw[h]));
            float ratio  = -0.25f + 0.5f / (1.0f + expf(-rw[h]));
            float lt = 1.0f / period + 2.0f * ratio - 0.25f + 0.5f;
            a += (span + 32.0f) * lt;
        }
        out[YELEMS] = 2e-6f * a / (float)HH;
    }
}

// ---------------------------------------------------------------------------
extern "C" void kernel_launch(void* const* d_in, const int* in_sizes, int n_in,
                              void* d_out, int out_size)
{
    const float* x       = (const float*)d_in[0];
    const float* w_attn  = (const float*)d_in[1];
    const float* b_attn  = (const float*)d_in[2];
    const float* w_proj  = (const float*)d_in[3];
    const float* b_proj  = (const float*)d_in[4];
    const float* span_p  = (const float*)d_in[5];
    const float* per_w   = (const float*)d_in[6];
    const float* rat_w   = (const float*)d_in[7];
    float* out = (float*)d_out;

    float *qkvp, *yattp, *maskp, *gxp, *gwap, *gwpp;
    cudaGetSymbolAddress((void**)&qkvp, g_qkv);
    cudaGetSymbolAddress((void**)&yattp, g_yatt);
    cudaGetSymbolAddress((void**)&maskp, g_mask);
    cudaGetSymbolAddress((void**)&gxp, g_x);
    cudaGetSymbolAddress((void**)&gwap, g_wa);
    cudaGetSymbolAddress((void**)&gwpp, g_wp);

    const int ATTN_SMEM = (BQ * QPSTR + 64 * 64 * 2 + TT) * (int)sizeof(float);
    cudaFuncSetAttribute(attn_mma, cudaFuncAttributeMaxDynamicSharedMemorySize, ATTN_SMEM);
    cudaFuncSetAttribute(gemm_cp, cudaFuncAttributeMaxDynamicSharedMemorySize, GEMM_SMEM);

    // pre-permute + tf32-round operands
    permA<<<(MM * CC / 8 + 255) / 256, 256>>>(x, gxp, MM * CC / 8);
    permW<<<(CC * C3 / 4 + 255) / 256, 256>>>(w_attn, gwap, CC, C3);
    permW<<<(CC * CC / 4 + 255) / 256, 256>>>(w_proj, gwpp, CC, CC);
    maskgen<<<HH, 256>>>(span_p, per_w, rat_w, maskp);

    // 1. QKV projection (perm3 output for attention chain)
    gemm_cp<<<dim3(C3 / 256, MM / 128), 256, GEMM_SMEM>>>(
        gxp, gwap, b_attn, qkvp, MM, C3, CC, 1);
    // 2. attention (emits y_att already in proj A layout, tf32-rounded)
    attn_mma<<<dim3(TT / BQ, HH, BB), 256, ATTN_SMEM>>>(qkvp, span_p, maskp, yattp);
    // 3. output projection (natural output)
    gemm_cp<<<dim3(CC / 256, MM / 128), 256, GEMM_SMEM>>>(
        yattp, gwpp, b_proj, out, MM, CC, CC, 0);
    // 4. span loss scalar
    loss_kernel<<<1, 32>>>(span_p, per_w, rat_w, out, out_size);
}

// round 11
// speedup vs baseline: 3.6457x; 1.1688x over previous
#include <cuda_runtime.h>
#include <math.h>

#define BB 2
#define TT 2048
#define CC 1024
#define HH 16
#define C3 3072
#define MM (BB*TT)          // 4096
#define YELEMS (BB*TT*CC)   // 4194304

#define BQ 128
#define QPSTR 72

// scratch (static device arrays: allocation-free)
__device__ float g_qkv[MM * C3];   // [B*T, 3C]  (n within-8 perm3'd, tf32-rounded)
__device__ float g_yatt[MM * CC];  // [B*T, C]   (position space = proj A layout, tf32)
__device__ float g_mask[HH * TT];  // [H, rel]
__device__ float g_x[MM * CC];     // x, k-perm3'd, tf32-rounded
__device__ float g_wa[CC * C3];    // w_attn, n B-permuted, tf32-rounded
__device__ float g_wp[CC * CC];    // w_proj, n B-permuted, tf32-rounded

__device__ __forceinline__ int perm3d(int p) { return ((p & 3) << 1) | (p >> 2); }

// attention K/V smem swizzle table P[r] packed as nibbles: {0,3,5,6,1,2,4,7}
#define PTAB 0x74216530u

__device__ __forceinline__ unsigned f2tf32(float x) {
    unsigned r;
    asm("cvt.rna.tf32.f32 %0, %1;" : "=r"(r) : "f"(x));
    return r;
}
__device__ __forceinline__ float f2tf32f(float x) {
    return __uint_as_float(f2tf32(x));
}

__device__ __forceinline__ void mma_tf32(float c[4], unsigned a0, unsigned a1,
                                         unsigned a2, unsigned a3,
                                         unsigned b0, unsigned b1) {
    asm volatile(
        "mma.sync.aligned.m16n8k8.row.col.f32.tf32.tf32.f32 "
        "{%0,%1,%2,%3}, {%4,%5,%6,%7}, {%8,%9}, {%0,%1,%2,%3};"
        : "+f"(c[0]), "+f"(c[1]), "+f"(c[2]), "+f"(c[3])
        : "r"(a0), "r"(a1), "r"(a2), "r"(a3), "r"(b0), "r"(b1));
}

// FFMA-only exp2 for z <= 0 (clamped at -80). No MUFU.
__device__ __forceinline__ float fexp2(float z) {
    z = fmaxf(z, -80.0f);
    float r = z + 12582912.0f;
    int zi = __float_as_int(r) - 0x4B400000;
    float f = z - (r - 12582912.0f);
    float p = 1.3333558e-3f;
    p = fmaf(p, f, 9.6181291e-3f);
    p = fmaf(p, f, 5.5504109e-2f);
    p = fmaf(p, f, 2.4022651e-1f);
    p = fmaf(p, f, 6.9314718e-1f);
    p = fmaf(p, f, 1.0f);
    return __int_as_float(__float_as_int(p) + (zi << 23));
}

#define CP16(dst, src) \
    asm volatile("cp.async.cg.shared.global [%0], [%1], 16;" :: "r"(dst), "l"(src))
#define CP_COMMIT() asm volatile("cp.async.commit_group;" ::: "memory")
#define CP_WAIT2()  asm volatile("cp.async.wait_group 2;" ::: "memory")
#define CP_WAIT1()  asm volatile("cp.async.wait_group 1;" ::: "memory")
#define CP_WAIT0()  asm volatile("cp.async.wait_group 0;" ::: "memory")

// ---------------------------------------------------------------------------
// pre-permute kernels (tf32-round so cp.async carries exact tf32)
// ---------------------------------------------------------------------------
__global__ void permA(const float* __restrict__ in, float* __restrict__ out, int total8)
{
    int idx = blockIdx.x * blockDim.x + threadIdx.x;
    if (idx >= total8) return;
    const float4* s = (const float4*)(in + (size_t)idx * 8);
    float4 v0 = s[0], v1 = s[1];
    float4 o0 = {f2tf32f(v0.x), f2tf32f(v1.x), f2tf32f(v0.y), f2tf32f(v1.y)};
    float4 o1 = {f2tf32f(v0.z), f2tf32f(v1.z), f2tf32f(v0.w), f2tf32f(v1.w)};
    float4* d = (float4*)(out + (size_t)idx * 8);
    d[0] = o0; d[1] = o1;
}

__global__ void permW(const float* __restrict__ in, float* __restrict__ out, int K, int N)
{
    int idx = blockIdx.x * blockDim.x + threadIdx.x;
    int total4 = K * (N >> 2);
    if (idx >= total4) return;
    int nq = idx % (N >> 2);
    int k  = idx / (N >> 2);
    int np = nq * 4;
    int blk = np & ~127;
    int p = np & 127;
    int hi = p & 64;
    int nlow = (p >> 3) & 7;
    int e0 = p & 7;
    const float* row = in + (size_t)k * N + blk;
    float4 o;
    o.x = f2tf32f(row[hi + ((e0 + 0) << 3) + nlow]);
    o.y = f2tf32f(row[hi + ((e0 + 1) << 3) + nlow]);
    o.z = f2tf32f(row[hi + ((e0 + 2) << 3) + nlow]);
    o.w = f2tf32f(row[hi + ((e0 + 3) << 3) + nlow]);
    *(float4*)(out + (size_t)k * N + np) = o;
}

// ---------------------------------------------------------------------------
// cp.async 4-stage tf32 GEMM (unchanged structure from R10-pass).
// permOut=1 additionally tf32-rounds (qkv feeds attention raw).
// ---------------------------------------------------------------------------
#define KS 32
#define ASTGF (128 * 32)
#define BSTGF (32 * 256)
#define NSTG 4
#define GEMM_SMEM ((NSTG * (ASTGF + BSTGF)) * 4)   // 196608 bytes

__device__ __forceinline__ void gemm_copy_stage(
    unsigned abase, unsigned bbase,
    const float* __restrict__ A, const float* __restrict__ W,
    int m0, int n0, int k0, int K, int N, int tid)
{
    const int r8 = tid >> 3, c8 = tid & 7;
#pragma unroll
    for (int u = 0; u < 4; u++) {
        int row = r8 + 32 * u;
        int phys = c8 ^ (row & 7);
        unsigned dst = abase + (unsigned)(row * 32 + phys * 4) * 4u;
        const float* src = A + (size_t)(m0 + row) * K + k0 + c8 * 4;
        CP16(dst, src);
    }
#pragma unroll
    for (int u = 0; u < 8; u++) {
        int c = c8 + 8 * u;
        int phys = (c & ~7) | ((c ^ (r8 & 7)) & 7);
        unsigned dst = bbase + (unsigned)(r8 * 256 + phys * 4) * 4u;
        const float* src = W + (size_t)(k0 + r8) * N + n0 + c * 4;
        CP16(dst, src);
    }
    CP_COMMIT();
}

__global__ __launch_bounds__(256, 1) void gemm_cp(
    const float* __restrict__ A, const float* __restrict__ W,
    const float* __restrict__ bias, float* __restrict__ out,
    int M, int N, int K, int permOut)
{
    extern __shared__ float gs[];
    float* Asm = gs;
    float* Bsm = gs + NSTG * ASTGF;
    unsigned abase0 = (unsigned)__cvta_generic_to_shared(Asm);
    unsigned bbase0 = (unsigned)__cvta_generic_to_shared(Bsm);

    const int tid = threadIdx.x, lane = tid & 31, w = tid >> 5;
    const int wM = w >> 2, wN = w & 3;
    const int g = lane >> 2, tig = lane & 3;
    const int m0 = blockIdx.y * 128, n0 = blockIdx.x * 256;
    const int NIT = K / KS;

    float acc[4][8][4];
#pragma unroll
    for (int i = 0; i < 4; i++)
#pragma unroll
        for (int j = 0; j < 8; j++)
#pragma unroll
            for (int c = 0; c < 4; c++) acc[i][j][c] = 0.0f;

#pragma unroll
    for (int s = 0; s < NSTG - 1; s++)
        gemm_copy_stage(abase0 + s * ASTGF * 4, bbase0 + s * BSTGF * 4,
                        A, W, m0, n0, s * KS, K, N, tid);

    for (int it = 0; it < NIT; it++) {
        CP_WAIT2();
        __syncthreads();

        const float* as = Asm + (it & (NSTG - 1)) * ASTGF;
        const float* bs = Bsm + (it & (NSTG - 1)) * BSTGF;

#pragma unroll
        for (int ka = 0; ka < 4; ka++) {
            unsigned a[4][4];
            {
                int c0 = 2 * ka + (tig >> 1);
                int aoff = (tig & 1) * 2;
                int physA = (c0 ^ g) * 4 + aoff;
#pragma unroll
                for (int i = 0; i < 4; i++) {
                    int R = wM * 64 + i * 16 + g;
                    float2 v0 = *(const float2*)&as[R * 32 + physA];
                    float2 v1 = *(const float2*)&as[(R + 8) * 32 + physA];
                    a[i][0] = __float_as_uint(v0.x);
                    a[i][1] = __float_as_uint(v1.x);
                    a[i][2] = __float_as_uint(v0.y);
                    a[i][3] = __float_as_uint(v1.y);
                }
            }
            unsigned b0[8], b1[8];
            {
                int cb = wN * 16 + 2 * g;
                int kr0 = 8 * ka + tig, kr1 = kr0 + 4;
                int t0 = tig, t1 = (tig + 4) & 7;
                float4 p0 = *(const float4*)&bs[kr0 * 256 + ((cb & ~7) | ((cb ^ t0) & 7)) * 4];
                float4 p1 = *(const float4*)&bs[kr0 * 256 + (((cb + 1) & ~7) | (((cb + 1) ^ t0) & 7)) * 4];
                float4 q0 = *(const float4*)&bs[kr1 * 256 + ((cb & ~7) | ((cb ^ t1) & 7)) * 4];
                float4 q1 = *(const float4*)&bs[kr1 * 256 + (((cb + 1) & ~7) | (((cb + 1) ^ t1) & 7)) * 4];
                b0[0] = __float_as_uint(p0.x); b0[1] = __float_as_uint(p0.y);
                b0[2] = __float_as_uint(p0.z); b0[3] = __float_as_uint(p0.w);
                b0[4] = __float_as_uint(p1.x); b0[5] = __float_as_uint(p1.y);
                b0[6] = __float_as_uint(p1.z); b0[7] = __float_as_uint(p1.w);
                b1[0] = __float_as_uint(q0.x); b1[1] = __float_as_uint(q0.y);
                b1[2] = __float_as_uint(q0.z); b1[3] = __float_as_uint(q0.w);
                b1[4] = __float_as_uint(q1.x); b1[5] = __float_as_uint(q1.y);
                b1[6] = __float_as_uint(q1.z); b1[7] = __float_as_uint(q1.w);
            }
#pragma unroll
            for (int i = 0; i < 4; i++)
#pragma unroll
                for (int j = 0; j < 8; j++)
                    mma_tf32(acc[i][j], a[i][0], a[i][1], a[i][2], a[i][3],
                             b0[j], b1[j]);
        }

        int nxt = it + NSTG - 1;
        if (nxt < NIT) {
            int s = nxt & (NSTG - 1);
            gemm_copy_stage(abase0 + s * ASTGF * 4, bbase0 + s * BSTGF * 4,
                            A, W, m0, n0, nxt * KS, K, N, tid);
        } else {
            CP_COMMIT();
        }
    }

#pragma unroll
    for (int i = 0; i < 4; i++) {
#pragma unroll
        for (int j = 0; j < 8; j++) {
            int row = m0 + wM * 64 + i * 16 + g;
            int col = n0 + wN * 64 + j * 8 + 2 * tig;
            float bx = bias[col], by = bias[col + 1];
            float v0 = acc[i][j][0] + bx, v1 = acc[i][j][1] + by;
            float v2 = acc[i][j][2] + bx, v3 = acc[i][j][3] + by;
            if (permOut) {
                int p0 = (col & ~7) | perm3d(col & 7);
                int p1 = (col & ~7) | perm3d((col + 1) & 7);
                out[(size_t)row * N + p0] = f2tf32f(v0);
                out[(size_t)row * N + p1] = f2tf32f(v1);
                out[(size_t)(row + 8) * N + p0] = f2tf32f(v2);
                out[(size_t)(row + 8) * N + p1] = f2tf32f(v3);
            } else {
                float2 o0 = {v0, v1}, o1 = {v2, v3};
                *(float2*)&out[(size_t)row * N + col] = o0;
                *(float2*)&out[(size_t)(row + 8) * N + col] = o1;
            }
        }
    }
}

// ---------------------------------------------------------------------------
// mask table
// ---------------------------------------------------------------------------
__global__ void maskgen(const float* __restrict__ sp, const float* __restrict__ pw,
                        const float* __restrict__ rw, float* __restrict__ mask)
{
    int h = blockIdx.x;
    float span   = 2048.0f / (1.0f + __expf(-sp[h]));
    float period = 2.0f + 2.0f / (1.0f + __expf(-pw[h]));
    float ratio  = -0.25f + 0.5f / (1.0f + __expf(-rw[h]));
    float amp = period * 0.25f, offs = period * ratio;
    for (int rel = threadIdx.x; rel < TT; rel += blockDim.x) {
        float relf = (float)rel;
        float mpos = fminf(fmaxf((32.0f - relf + span) * 0.03125f, 0.0f), 1.0f);
        float wave = 0.5f * (cosf(6.283185307179586f * relf / period) + 1.0f) * amp
                     + 0.5f + offs;
        wave = fminf(fmaxf(wave, 0.0f), 1.0f);
        mask[h * TT + rel] = mpos * wave;
    }
}

// ---------------------------------------------------------------------------
// Tensor-core flash attention, cp.async double-buffered K/V.
// K/V smem tiles are RAW row copies of (perm3'd, tf32) qkv with per-row
// XOR-nibble swizzle P (conflict-free for cp stores, K LDS.64, V LDS.128).
// S: slot tig reads positions 8ks+2tig(+1) = logical d 8ks+tig(+4) == Q slots.
// PV: mma a's n-columns = positions {8p+a}; O epilogue writes position space,
// which is exactly proj's pre-permuted A layout.
// ---------------------------------------------------------------------------
#define KVST 4096   // floats per K (or V) stage

__device__ __forceinline__ void attn_copy_kv(
    unsigned kvbase, const float* __restrict__ qkv,
    int b, int h, int j0, int tid)
{
    int r = tid >> 2, q4 = tid & 3;
    int Pr = (PTAB >> (4 * (r & 7))) & 15;
    const float* kp = qkv + ((size_t)(b * TT + j0 + r) * C3 + CC + h * 64);
#pragma unroll
    for (int u = 0; u < 4; u++) {
        int lc = q4 + 4 * u;
        int pc = (lc & 8) | ((lc ^ Pr) & 7);
        unsigned off = (unsigned)(r * 64 + pc * 4) * 4u;
        CP16(kvbase + off, kp + lc * 4);
        CP16(kvbase + KVST * 4u + off, kp + CC + lc * 4);
    }
    CP_COMMIT();
}

__global__ __launch_bounds__(256) void attn_mma(
    const float* __restrict__ qkv, const float* __restrict__ span_p,
    const float* __restrict__ gmask, float* __restrict__ yout)
{
    extern __shared__ float sm[];
    float* QP = sm;                        // 128 x 72 (Q staging, then P)
    float* KV = sm + BQ * QPSTR;           // 2 stages x (K 4096 | V 4096)
    float* MT = KV + 4 * KVST;             // 2048 mask entries

    const int tid = threadIdx.x, lane = tid & 31, w = tid >> 5;
    const int g = lane >> 2, tig = lane & 3;
    const int i0 = ((int)gridDim.x - 1 - (int)blockIdx.x) * BQ;
    const int h = blockIdx.y, b = blockIdx.z;
    const int R = w * 16;
    const int pg  = (PTAB >> (4 * g)) & 15;
    const int pt0 = (PTAB >> (4 * tig)) & 15;
    const int pt1 = (PTAB >> (4 * (tig + 4))) & 15;
    unsigned kvbase = (unsigned)__cvta_generic_to_shared(KV);

    const float span = 2048.0f / (1.0f + __expf(-span_p[h]));
    int jstart = 0;
    {
        float thr = (float)i0 - span - 96.0f;
        if (thr > 0.0f) jstart = ((int)thr / 64) * 64;
    }
    const int ntiles = (i0 + 64 - jstart) / 64 + 1;

    // kick off tile 0 copy immediately
    attn_copy_kv(kvbase, qkv, b, h, jstart, tid);

    for (int t = tid; t < TT; t += 256) MT[t] = gmask[h * TT + t];

    // stage Q (gmem already perm3'd + tf32), scaled to log2 domain
    {
        const float SC = 0.125f * 1.4426950408889634f;
        int row = tid >> 1, cb = (tid & 1) * 32;
        const float* src = &qkv[(size_t)(b * TT + i0 + row) * C3 + h * 64 + cb];
#pragma unroll
        for (int u = 0; u < 8; u++) {
            float4 v = *(const float4*)&src[u * 4];
            float4 o = {f2tf32f(v.x * SC), f2tf32f(v.y * SC),
                        f2tf32f(v.z * SC), f2tf32f(v.w * SC)};
            *(float4*)&QP[row * QPSTR + cb + u * 4] = o;
        }
    }
    __syncthreads();

    unsigned qf[8][4];
#pragma unroll
    for (int ks = 0; ks < 8; ks++) {
        float2 v0 = *(const float2*)&QP[(R + g) * QPSTR + 8 * ks + 2 * tig];
        float2 v1 = *(const float2*)&QP[(R + g + 8) * QPSTR + 8 * ks + 2 * tig];
        qf[ks][0] = __float_as_uint(v0.x);
        qf[ks][1] = __float_as_uint(v1.x);
        qf[ks][2] = __float_as_uint(v0.y);
        qf[ks][3] = __float_as_uint(v1.y);
    }

    float O[8][4];
#pragma unroll
    for (int a = 0; a < 8; a++)
#pragma unroll
        for (int c = 0; c < 4; c++) O[a][c] = 0.0f;
    float mr[2] = {-1e30f, -1e30f}, lr[2] = {0.0f, 0.0f};

    const int irow[2] = {i0 + R + g, i0 + R + g + 8};

    for (int ti = 0; ti < ntiles; ti++) {
        const int j0 = jstart + ti * 64;
        __syncthreads();   // readers of the stage being overwritten are done
        if (ti + 1 < ntiles) {
            attn_copy_kv(kvbase + ((unsigned)((ti + 1) & 1)) * 2 * KVST * 4u,
                         qkv, b, h, j0 + 64, tid);
            CP_WAIT1();
        } else {
            CP_WAIT0();
        }
        __syncthreads();   // stage ti visible to all

        const float* Ks = KV + (ti & 1) * 2 * KVST;
        const float* Vs = Ks + KVST;

        // S = Q @ K^T
        float S[8][4];
#pragma unroll
        for (int a = 0; a < 8; a++)
#pragma unroll
            for (int c = 0; c < 4; c++) S[a][c] = 0.0f;
#pragma unroll
        for (int ks = 0; ks < 8; ks++) {
            int c4 = 2 * ks + (tig >> 1);
            int phys = (c4 & 8) | ((c4 ^ pg) & 7);
            int coff = phys * 4 + 2 * (tig & 1);
            unsigned b0[8], b1[8];
#pragma unroll
            for (int a = 0; a < 8; a++) {
                float2 kk = *(const float2*)&Ks[(8 * a + g) * 64 + coff];
                b0[a] = __float_as_uint(kk.x);
                b1[a] = __float_as_uint(kk.y);
            }
#pragma unroll
            for (int a = 0; a < 8; a++)
                mma_tf32(S[a], qf[ks][0], qf[ks][1], qf[ks][2], qf[ks][3],
                         b0[a], b1[a]);
        }

        // online softmax (key mapping unchanged: mma a covers keys 8a..8a+7)
#pragma unroll
        for (int r = 0; r < 2; r++) {
            float tmax = -1e30f;
#pragma unroll
            for (int a = 0; a < 8; a++) {
                tmax = fmaxf(tmax, S[a][2 * r]);
                tmax = fmaxf(tmax, S[a][2 * r + 1]);
            }
            tmax = fmaxf(tmax, __shfl_xor_sync(0xffffffffu, tmax, 1));
            tmax = fmaxf(tmax, __shfl_xor_sync(0xffffffffu, tmax, 2));
            float mnew = fmaxf(mr[r], tmax);
            float corr = fexp2(mr[r] - mnew);
            mr[r] = mnew;
            float rsum = 0.0f;
            int prow = (R + g + 8 * r) * QPSTR;
#pragma unroll
            for (int a = 0; a < 8; a++) {
#pragma unroll
                for (int c = 0; c < 2; c++) {
                    int j = j0 + 8 * a + 2 * tig + c;
                    int rel = irow[r] - j;
                    float p = 0.0f;
                    if (rel >= 0)
                        p = fexp2(S[a][2 * r + c] - mnew) * MT[rel];
                    rsum += p;
                    int p8 = 2 * tig + c;
                    int col = 8 * a + (((p8 & 3) << 1) | (p8 >> 2));
                    QP[prow + col] = f2tf32f(p);
                }
            }
            rsum += __shfl_xor_sync(0xffffffffu, rsum, 1);
            rsum += __shfl_xor_sync(0xffffffffu, rsum, 2);
            lr[r] = lr[r] * corr + rsum;
#pragma unroll
            for (int a = 0; a < 8; a++) {
                O[a][2 * r] *= corr;
                O[a][2 * r + 1] *= corr;
            }
        }
        __syncwarp();

        // O += P @ V  (raw V rows; mma a's n-cols = positions 8p+a)
#pragma unroll
        for (int ks = 0; ks < 8; ks++) {
            float2 v0 = *(const float2*)&QP[(R + g) * QPSTR + 8 * ks + 2 * tig];
            float2 v1 = *(const float2*)&QP[(R + g + 8) * QPSTR + 8 * ks + 2 * tig];
            unsigned a0 = __float_as_uint(v0.x), a1 = __float_as_uint(v1.x);
            unsigned a2 = __float_as_uint(v0.y), a3 = __float_as_uint(v1.y);
            int rv0 = (8 * ks + tig) * 64, rv1 = (8 * ks + tig + 4) * 64;
            int c0 = 2 * g, c1 = 2 * g + 1;
            float4 p0 = *(const float4*)&Vs[rv0 + ((c0 & 8) | ((c0 ^ pt0) & 7)) * 4];
            float4 p1 = *(const float4*)&Vs[rv0 + ((c1 & 8) | ((c1 ^ pt0) & 7)) * 4];
            float4 q0 = *(const float4*)&Vs[rv1 + ((c0 & 8) | ((c0 ^ pt1) & 7)) * 4];
            float4 q1 = *(const float4*)&Vs[rv1 + ((c1 & 8) | ((c1 ^ pt1) & 7)) * 4];
            unsigned b0[8], b1[8];
            b0[0] = __float_as_uint(p0.x); b0[1] = __float_as_uint(p0.y);
            b0[2] = __float_as_uint(p0.z); b0[3] = __float_as_uint(p0.w);
            b0[4] = __float_as_uint(p1.x); b0[5] = __float_as_uint(p1.y);
            b0[6] = __float_as_uint(p1.z); b0[7] = __float_as_uint(p1.w);
            b1[0] = __float_as_uint(q0.x); b1[1] = __float_as_uint(q0.y);
            b1[2] = __float_as_uint(q0.z); b1[3] = __float_as_uint(q0.w);
            b1[4] = __float_as_uint(q1.x); b1[5] = __float_as_uint(q1.y);
            b1[6] = __float_as_uint(q1.z); b1[7] = __float_as_uint(q1.w);
#pragma unroll
            for (int a = 0; a < 8; a++)
                mma_tf32(O[a], a0, a1, a2, a3, b0[a], b1[a]);
        }
    }

    // epilogue: O[a][c] = position 16*tig + 8*(c&1) + a; tf32-round for proj
    float inv0 = 1.0f / lr[0], inv1 = 1.0f / lr[1];
    float* y0 = &yout[(size_t)(b * TT + irow[0]) * CC + h * 64];
    float* y1 = &yout[(size_t)(b * TT + irow[1]) * CC + h * 64];
#pragma unroll
    for (int a = 0; a < 8; a++) {
        int cb = 16 * tig + a;
        y0[cb]     = f2tf32f(O[a][0] * inv0);
        y0[cb + 8] = f2tf32f(O[a][1] * inv0);
        y1[cb]     = f2tf32f(O[a][2] * inv1);
        y1[cb + 8] = f2tf32f(O[a][3] * inv1);
    }
}

// ---------------------------------------------------------------------------
__global__ void loss_kernel(const float* __restrict__ sp, const float* __restrict__ pw,
                            const float* __restrict__ rw, float* __restrict__ out,
                            int out_size)
{
    if (threadIdx.x == 0 && blockIdx.x == 0 && out_size > YELEMS) {
        float a = 0.0f;
        for (int h = 0; h < HH; h++) {
            float span   = 2048.0f / (1.0f + expf(-sp[h]));
            float period = 2.0f + 2.0f / (1.0f + expf(-pw[h]));
            float ratio  = -0.25f + 0.5f / (1.0f + expf(-rw[h]));
            float lt = 1.0f / period + 2.0f * ratio - 0.25f + 0.5f;
            a += (span + 32.0f) * lt;
        }
        out[YELEMS] = 2e-6f * a / (float)HH;
    }
}

// ---------------------------------------------------------------------------
extern "C" void kernel_launch(void* const* d_in, const int* in_sizes, int n_in,
                              void* d_out, int out_size)
{
    const float* x       = (const float*)d_in[0];
    const float* w_attn  = (const float*)d_in[1];
    const float* b_attn  = (const float*)d_in[2];
    const float* w_proj  = (const float*)d_in[3];
    const float* b_proj  = (const float*)d_in[4];
    const float* span_p  = (const float*)d_in[5];
    const float* per_w   = (const float*)d_in[6];
    const float* rat_w   = (const float*)d_in[7];
    float* out = (float*)d_out;

    float *qkvp, *yattp, *maskp, *gxp, *gwap, *gwpp;
    cudaGetSymbolAddress((void**)&qkvp, g_qkv);
    cudaGetSymbolAddress((void**)&yattp, g_yatt);
    cudaGetSymbolAddress((void**)&maskp, g_mask);
    cudaGetSymbolAddress((void**)&gxp, g_x);
    cudaGetSymbolAddress((void**)&gwap, g_wa);
    cudaGetSymbolAddress((void**)&gwpp, g_wp);

    const int ATTN_SMEM = (BQ * QPSTR + 4 * KVST + TT) * (int)sizeof(float);  // 110592
    cudaFuncSetAttribute(attn_mma, cudaFuncAttributeMaxDynamicSharedMemorySize, ATTN_SMEM);
    cudaFuncSetAttribute(gemm_cp, cudaFuncAttributeMaxDynamicSharedMemorySize, GEMM_SMEM);

    // pre-permute + tf32-round operands
    permA<<<(MM * CC / 8 + 255) / 256, 256>>>(x, gxp, MM * CC / 8);
    permW<<<(CC * C3 / 4 + 255) / 256, 256>>>(w_attn, gwap, CC, C3);
    permW<<<(CC * CC / 4 + 255) / 256, 256>>>(w_proj, gwpp, CC, CC);
    maskgen<<<HH, 256>>>(span_p, per_w, rat_w, maskp);

    // 1. QKV projection (perm3 + tf32 output for attention chain)
    gemm_cp<<<dim3(C3 / 256, MM / 128), 256, GEMM_SMEM>>>(
        gxp, gwap, b_attn, qkvp, MM, C3, CC, 1);
    // 2. attention (cp.async K/V pipeline; emits y_att in proj A layout)
    attn_mma<<<dim3(TT / BQ, HH, BB), 256, ATTN_SMEM>>>(qkvp, span_p, maskp, yattp);
    // 3. output projection (natural output)
    gemm_cp<<<dim3(CC / 256, MM / 128), 256, GEMM_SMEM>>>(
        yattp, gwpp, b_proj, out, MM, CC, CC, 0);
    // 4. span loss scalar
    loss_kernel<<<1, 32>>>(span_p, per_w, rat_w, out, out_size);
}